// round 14
// baseline (speedup 1.0000x reference)
#include <cuda_runtime.h>
#include <cuda_fp16.h>
#include <math.h>
#include <stdint.h>

#define NN 4096
#define ND 256
#define HID 64
#define NH 4
#define NC 16

// ---------------- scratch (static device globals) ---------------------------
__device__ float  g_H1[NN*ND];
__device__ float  g_F1[NH*NN];
__device__ float  g_F2[NH*NN];
__device__ unsigned g_f2max1u[NH];
__device__ uint8_t g_adj8[(size_t)NN*NN];
__device__ uint4  g_bd1h[NH*2048];           // per j-pair packed half2 {f2,B,D,0}
__device__ __half g_Vb[(size_t)NH*NN*80];    // [head][j][80] (col64 = ones)
__device__ float  g_H2[NN*ND];
__device__ float  g_G2[NN*NC];
__device__ __half g_G2b[NN*32];              // [j][32] (col16 = ones)
__device__ uint4  g_bd2h[2048];
__device__ float  g_f1b[NN];
__device__ float  g_f2b[NN];
__device__ unsigned g_f2max2u[1];

// ---------------- helpers -----------------------------------------------------
__device__ __forceinline__ unsigned fenc(float f){
    unsigned u = __float_as_uint(f);
    return (u & 0x80000000u) ? ~u : (u | 0x80000000u);
}
__device__ __forceinline__ float fdec(unsigned u){
    return (u & 0x80000000u) ? __uint_as_float(u ^ 0x80000000u) : __uint_as_float(~u);
}
__device__ __forceinline__ uint32_t pack2f(float a, float b){
    __half2 h = __floats2half2_rn(a, b);
    return *reinterpret_cast<uint32_t*>(&h);
}
__device__ __forceinline__ __half2 u2h(uint32_t u){ return *reinterpret_cast<__half2*>(&u); }
__device__ __forceinline__ uint32_t h2u(__half2 h){ return *reinterpret_cast<uint32_t*>(&h); }

__device__ __forceinline__ uint32_t wgt_h2(uint32_t f1r2, uint32_t gp2, uint32_t gn2,
                                           const uint4& T){
    __half2 s2 = __hadd2(u2h(f1r2), u2h(T.x));
    uint32_t m = __hgt2_mask(s2, __float2half2_rn(0.f));
    uint32_t wp = h2u(__hmul2(u2h(gp2), u2h(T.y)));
    uint32_t wn = h2u(__hmul2(u2h(gn2), u2h(T.z)));
    return (wp & m) | (wn & ~m);
}
__device__ __forceinline__ uint32_t bmask(uint32_t v){
    return (v & 0xFFu)*0xFFFFu | ((v >> 8) & 0xFFu)*0xFFFF0000u;
}
// k-slot p (0..15) -> original j within 16-group, chosen so thread tg's four
// k slots {2tg,2tg+1,8+2tg,8+2tg+1} map to j {4tg,4tg+1,4tg+2,4tg+3}
__device__ __forceinline__ int permj(int p){
    return 4*((p & 7) >> 1) + ((p & 8) ? 2 : 0) + (p & 1);
}

#define MMA16816(C, a0,a1,a2,a3, b0,b1) \
    asm volatile("mma.sync.aligned.m16n8k16.row.col.f32.f16.f16.f32 " \
        "{%0,%1,%2,%3}, {%4,%5,%6,%7}, {%8,%9}, {%0,%1,%2,%3};" \
        : "+f"((C)[0]), "+f"((C)[1]), "+f"((C)[2]), "+f"((C)[3]) \
        : "r"(a0), "r"(a1), "r"(a2), "r"(a3), "r"(b0), "r"(b1))

#define LDSM_X4T(b0,b1,b2,b3, addr) \
    asm volatile("ldmatrix.sync.aligned.m8n8.x4.trans.shared.b16 {%0,%1,%2,%3}, [%4];" \
        : "=r"(b0), "=r"(b1), "=r"(b2), "=r"(b3) : "r"(addr))

// ---------------- K0: adjacency -> bytes (+ init atomic cells) ----------------
__global__ void adj8_kernel(const int* __restrict__ adj){
    if (blockIdx.x == 0 && threadIdx.x <= NH){
        if (threadIdx.x < NH) g_f2max1u[threadIdx.x] = 0u;
        else g_f2max2u[0] = 0u;
    }
    size_t idx = (size_t)blockIdx.x*256 + threadIdx.x;   // grid 4096
    const int4* s = reinterpret_cast<const int4*>(adj) + idx*4;
    uint32_t w[4];
#pragma unroll
    for (int q = 0; q < 4; q++){
        int4 v = s[q];
        w[q] = (v.x != 0 ? 1u : 0u) | (v.y != 0 ? 1u : 0u) << 8
             | (v.z != 0 ? 1u : 0u) << 16 | (v.w != 0 ? 1u : 0u) << 24;
    }
    reinterpret_cast<uint4*>(g_adj8)[idx] = make_uint4(w[0], w[1], w[2], w[3]);
}

// ---------------- K1: H1 = x @ W1^T, fused f1/f2 + per-head max ---------------
__global__ void gemm1_kernel(const float* __restrict__ X, const float* __restrict__ W,
                             const float* __restrict__ A1, const float* __restrict__ A2){
    __shared__ float sx[64][17];
    __shared__ float sw[64][17];
    __shared__ float sa1[64], sa2[64], smaxs[16];
    int tid = threadIdx.x;
    int tx = tid & 15, ty = tid >> 4;
    int mb = blockIdx.x * 64, h = blockIdx.y, nb = h * 64;
    if (tid < 64) sa1[tid] = A1[nb + tid];
    else if (tid < 128) sa2[tid - 64] = A2[nb + tid - 64];
    float acc[4][4] = {};
    for (int kb = 0; kb < ND; kb += 16){
        __syncthreads();
        for (int u = tid; u < 64*16; u += 256){
            int m = u >> 4, k = u & 15;
            sx[m][k] = X[(mb + m)*ND + kb + k];
        }
        for (int u = tid; u < 64*16; u += 256){
            int n = u >> 4, k = u & 15;
            sw[n][k] = W[(nb + n)*ND + kb + k];
        }
        __syncthreads();
#pragma unroll
        for (int k = 0; k < 16; k++){
            float a[4], b[4];
#pragma unroll
            for (int r = 0; r < 4; r++){ a[r] = sx[ty*4 + r][k]; b[r] = sw[tx*4 + r][k]; }
#pragma unroll
            for (int i = 0; i < 4; i++)
#pragma unroll
                for (int j = 0; j < 4; j++) acc[i][j] += a[i]*b[j];
        }
    }
#pragma unroll
    for (int i = 0; i < 4; i++)
#pragma unroll
        for (int j = 0; j < 4; j++)
            g_H1[(mb + ty*4 + i)*ND + nb + tx*4 + j] = acc[i][j];
    float a1v[4], a2v[4];
#pragma unroll
    for (int j = 0; j < 4; j++){ a1v[j] = sa1[tx*4 + j]; a2v[j] = sa2[tx*4 + j]; }
    float fmax_local = -INFINITY;
#pragma unroll
    for (int i = 0; i < 4; i++){
        float p1 = acc[i][0]*a1v[0] + acc[i][1]*a1v[1] + acc[i][2]*a1v[2] + acc[i][3]*a1v[3];
        float p2 = acc[i][0]*a2v[0] + acc[i][1]*a2v[1] + acc[i][2]*a2v[2] + acc[i][3]*a2v[3];
#pragma unroll
        for (int off = 8; off > 0; off >>= 1){
            p1 += __shfl_down_sync(0xffffffffu, p1, off, 16);
            p2 += __shfl_down_sync(0xffffffffu, p2, off, 16);
        }
        if (tx == 0){
            int row = mb + ty*4 + i;
            g_F1[h*NN + row] = p1;
            g_F2[h*NN + row] = p2;
            fmax_local = fmaxf(fmax_local, p2);
        }
    }
    if (tx == 0) smaxs[ty] = fmax_local;
    __syncthreads();
    if (tid == 0){
        float m = smaxs[0];
#pragma unroll
        for (int k = 1; k < 16; k++) m = fmaxf(m, smaxs[k]);
        atomicMax(&g_f2max1u[h], fenc(m));
    }
}

// ---------------- K2: V fp16 + ones column, packed bdf table ------------------
__global__ void vbf_kernel(){
    __shared__ float sf[64], sB[64], sD[64];
    int tid = threadIdx.x;            // grid (64, NH), 256 threads
    int jb = blockIdx.x, h = blockIdx.y;
    if (tid < 64){
        int j = jb*64 + tid;
        float f2 = g_F2[h*NN + j];
        float d  = f2 - fdec(g_f2max1u[h]);
        sf[tid] = f2; sB[tid] = expf(d); sD[tid] = expf(0.01f*d);
    }
    __syncthreads();
    if (tid < 32){
        uint4 T;
        T.x = pack2f(sf[2*tid], sf[2*tid + 1]);
        T.y = pack2f(sB[2*tid], sB[2*tid + 1]);
        T.z = pack2f(sD[2*tid], sD[2*tid + 1]);
        T.w = 0u;
        g_bd1h[h*2048 + jb*32 + tid] = T;
    }
    int j = jb*64 + (tid >> 2);
    int fg = tid & 3;
    const float4* src = reinterpret_cast<const float4*>(g_H1 + (size_t)j*ND + h*HID + fg*16);
    __half* dhi = g_Vb + ((size_t)h*NN + j)*80 + fg*16;
    uint32_t ph[8];
#pragma unroll
    for (int q = 0; q < 4; q++){
        float4 v = src[q];
        ph[q*2]   = pack2f(v.x, v.y);
        ph[q*2+1] = pack2f(v.z, v.w);
    }
    uint4* oh = reinterpret_cast<uint4*>(dhi);
    oh[0] = make_uint4(ph[0],ph[1],ph[2],ph[3]);
    oh[1] = make_uint4(ph[4],ph[5],ph[6],ph[7]);
    if (fg == 3){
        uint4* zh = reinterpret_cast<uint4*>(dhi + 16);
        zh[0] = make_uint4(0x00003C00u, 0u, 0u, 0u);
        zh[1] = make_uint4(0u, 0u, 0u, 0u);
    }
}

// ---------------- K3: attn1, register-direct A + mma.sync, permuted-j ---------
// grid (64, NH), 128 threads = 4 warps x 16 rows = 64 rows/block. K-tile 64 j.
// dyn smem: B[2][64][88]h perm rows (11264 ea) | adj[2][64 rows][80B] (5120 ea) | T[2][32]u4
#define A1_B(b)   (dsm + (b)*11264)
#define A1_ADJ(b) (dsm + 22528 + (b)*5120)
#define A1_T(b)   ((uint4*)(dsm + 32768 + (b)*512))
#define A1_TOT    33792

__global__ void __launch_bounds__(128) attn1_mma_kernel(){
    extern __shared__ __align__(16) unsigned char dsm[];
    float* sepi = (float*)dsm;
    int tid = threadIdx.x, w = tid >> 5, lane = tid & 31;
    int g = lane >> 2, tg = lane & 3;
    int row0 = blockIdx.x * 64, h = blockIdx.y;
    const __half* Vh = g_Vb + (size_t)h*NN*80;
    const uint4* bdg = g_bd1h + h*2048;
    uint32_t sbase = (uint32_t)__cvta_generic_to_shared(dsm);

    int rlo = w*16 + g, rhi = rlo + 8;
    float f1lo = g_F1[h*NN + row0 + rlo];
    float f1hi = g_F1[h*NN + row0 + rhi];
    float mx = fdec(g_f2max1u[h]);
    float tlo = f1lo + mx, thi = f1hi + mx;
    uint32_t f1lo2 = pack2f(f1lo, f1lo), f1hi2 = pack2f(f1hi, f1hi);
    float gplo = tlo >= 0.f ? 1.f : expf(0.99f*tlo);
    float gnlo = tlo >= 0.f ? expf(-0.99f*tlo) : 1.f;
    float gphi = thi >= 0.f ? 1.f : expf(0.99f*thi);
    float gnhi = thi >= 0.f ? expf(-0.99f*thi) : 1.f;
    uint32_t gplo2 = pack2f(gplo, gplo), gnlo2 = pack2f(gnlo, gnlo);
    uint32_t gphi2 = pack2f(gphi, gphi), gnhi2 = pack2f(gnhi, gnhi);

    // B-stage identity: smem row p <- global V row (permuted)
    int sp = tid >> 1, sch = tid & 1;
    int pj = (sp & 48) + permj(sp & 15);     // permuted j offset within tile

    float C[10][4] = {};

    // ---- prologue stage tile 0 ----
    {
        const uint4* src = reinterpret_cast<const uint4*>(Vh + (size_t)pj*80 + sch*40);
        uint4* dst = reinterpret_cast<uint4*>(A1_B(0) + sp*176 + sch*80);
#pragma unroll
        for (int q = 0; q < 5; q++) dst[q] = src[q];
        if (tid < 64){
            const uint4* as = reinterpret_cast<const uint4*>(g_adj8 + (size_t)(row0 + tid)*NN);
            uint4* ad = reinterpret_cast<uint4*>(A1_ADJ(0) + tid*80);
#pragma unroll
            for (int q = 0; q < 4; q++) ad[q] = as[q];
            if (tid < 32) A1_T(0)[tid] = bdg[tid];
        }
    }
    __syncthreads();

    for (int t = 0; t < 64; t++){
        int p = t & 1;
        if (t < 63){   // stage t+1 into buffer p^1
            const uint4* src = reinterpret_cast<const uint4*>(
                Vh + (size_t)((t+1)*64 + pj)*80 + sch*40);
            uint4* dst = reinterpret_cast<uint4*>(A1_B(p^1) + sp*176 + sch*80);
#pragma unroll
            for (int q = 0; q < 5; q++) dst[q] = src[q];
            if (tid < 64){
                const uint4* as = reinterpret_cast<const uint4*>(
                    g_adj8 + (size_t)(row0 + tid)*NN + (t+1)*64);
                uint4* ad = reinterpret_cast<uint4*>(A1_ADJ(p^1) + tid*80);
#pragma unroll
                for (int q = 0; q < 4; q++) ad[q] = as[q];
                if (tid < 32) A1_T(p^1)[tid] = bdg[(t+1)*32 + tid];
            }
        }
        // ---- compute tile t ----
        const uint4* sT = A1_T(p);
        const unsigned char* adjp = A1_ADJ(p);
        uint32_t Bb = sbase + p*11264;
#pragma unroll
        for (int ks = 0; ks < 4; ks++){
            uint4 T0 = sT[ks*8 + 2*tg];
            uint4 T1 = sT[ks*8 + 2*tg + 1];
            uint32_t vlo = *reinterpret_cast<const uint32_t*>(adjp + rlo*80 + ks*16 + tg*4);
            uint32_t vhi = *reinterpret_cast<const uint32_t*>(adjp + rhi*80 + ks*16 + tg*4);
            uint32_t a0 = wgt_h2(f1lo2, gplo2, gnlo2, T0) & bmask(vlo);
            uint32_t a1 = wgt_h2(f1hi2, gphi2, gnhi2, T0) & bmask(vhi);
            uint32_t a2 = wgt_h2(f1lo2, gplo2, gnlo2, T1) & bmask(vlo >> 16);
            uint32_t a3 = wgt_h2(f1hi2, gphi2, gnhi2, T1) & bmask(vhi >> 16);
            uint32_t lb = Bb + (ks*16 + (lane & 15))*176 + (lane >> 4)*16;
#pragma unroll
            for (int g5 = 0; g5 < 5; g5++){
                uint32_t b0, b1, b2, b3;
                LDSM_X4T(b0, b1, b2, b3, lb + g5*32);
                MMA16816(C[2*g5],     a0, a1, a2, a3, b0, b1);
                MMA16816(C[2*g5 + 1], a0, a1, a2, a3, b2, b3);
            }
        }
        __syncthreads();
    }
    // ---- epilogue: C -> sepi[64][80] ----
#pragma unroll
    for (int q = 0; q < 10; q++){
        sepi[rlo*80 + q*8 + 2*tg]     = C[q][0];
        sepi[rlo*80 + q*8 + 2*tg + 1] = C[q][1];
        sepi[rhi*80 + q*8 + 2*tg]     = C[q][2];
        sepi[rhi*80 + q*8 + 2*tg + 1] = C[q][3];
    }
    __syncthreads();
    {
        int r = tid >> 1, cg = (tid & 1)*32;
        float rz = 1.f / sepi[r*80 + 64];
        float* dst = g_H2 + (size_t)(row0 + r)*ND + h*HID + cg;
#pragma unroll
        for (int c = 0; c < 32; c += 4){
            float o[4];
#pragma unroll
            for (int e = 0; e < 4; e++){
                float v = sepi[r*80 + cg + c + e] * rz;
                o[e] = v > 0.f ? v : expm1f(v);
            }
            *reinterpret_cast<float4*>(dst + c) = make_float4(o[0], o[1], o[2], o[3]);
        }
    }
}

// ---------------- K4: G2 = H2 @ W2^T + f-vectors + fused max ------------------
__global__ void gemm2_kernel(const float* __restrict__ W2,
                             const float* __restrict__ a1, const float* __restrict__ a2){
    __shared__ float sW[16][257];
    __shared__ float sa1[16], sa2[16];
    __shared__ float s_u2[16];
    int tid = threadIdx.x;
    for (int u = tid; u < 16*256; u += 256) sW[u >> 8][u & 255] = W2[u];
    if (tid < 16){ sa1[tid] = a1[tid]; sa2[tid] = a2[tid]; }
    __syncthreads();
    int idx = blockIdx.x*256 + tid;
    int i = idx >> 4, c = idx & 15;
    const float4* hr = reinterpret_cast<const float4*>(g_H2 + i*ND);
    float acc = 0.f;
#pragma unroll 4
    for (int k4 = 0; k4 < 64; k4++){
        float4 v = hr[k4];
        acc += v.x*sW[c][k4*4] + v.y*sW[c][k4*4+1] + v.z*sW[c][k4*4+2] + v.w*sW[c][k4*4+3];
    }
    g_G2[idx] = acc;
    float u1 = acc*sa1[c], u2 = acc*sa2[c];
#pragma unroll
    for (int off = 8; off > 0; off >>= 1){
        u1 += __shfl_down_sync(0xffffffffu, u1, off, 16);
        u2 += __shfl_down_sync(0xffffffffu, u2, off, 16);
    }
    if (c == 0){ g_f1b[i] = u1; g_f2b[i] = u2; s_u2[tid >> 4] = u2; }
    __syncthreads();
    if (tid == 0){
        float m = s_u2[0];
#pragma unroll
        for (int k = 1; k < 16; k++) m = fmaxf(m, s_u2[k]);
        atomicMax(g_f2max2u, fenc(m));
    }
}

// ---------------- K5: packed bdf2 table + G2 fp16 split -----------------------
__global__ void bdf2g2_kernel(){
    int row = blockIdx.x*256 + threadIdx.x;   // grid 16
    float f2 = g_f2b[row];
    float d  = f2 - fdec(g_f2max2u[0]);
    float B = expf(d), D = expf(0.01f*d);
    float f2n = __shfl_down_sync(0xffffffffu, f2, 1);
    float Bn  = __shfl_down_sync(0xffffffffu, B, 1);
    float Dn  = __shfl_down_sync(0xffffffffu, D, 1);
    if (!(row & 1)){
        uint4 T;
        T.x = pack2f(f2, f2n); T.y = pack2f(B, Bn); T.z = pack2f(D, Dn); T.w = 0u;
        g_bd2h[row >> 1] = T;
    }
    const float4* src = reinterpret_cast<const float4*>(g_G2 + row*NC);
    uint32_t ph[16];
#pragma unroll
    for (int q = 0; q < 4; q++){
        float4 v = src[q];
        ph[q*2]   = pack2f(v.x, v.y);
        ph[q*2+1] = pack2f(v.z, v.w);
    }
    ph[8] = 0x00003C00u;
#pragma unroll
    for (int k = 9; k < 16; k++) ph[k] = 0u;
    uint4* dh = reinterpret_cast<uint4*>(g_G2b + (size_t)row*32);
#pragma unroll
    for (int k = 0; k < 4; k++)
        dh[k] = make_uint4(ph[4*k], ph[4*k+1], ph[4*k+2], ph[4*k+3]);
}

// ---------------- K6: attn2, register-direct A + mma.sync, permuted-j ---------
// grid 64, 128 threads = 4 warps x 16 rows.
#define A2_B(b)   (sm2 + (b)*5120)
#define A2_ADJ(b) (sm2 + 10240 + (b)*5120)
#define A2_T(b)   ((uint4*)(sm2 + 20480 + (b)*512))

__global__ void __launch_bounds__(128) attn2_mma_kernel(float* __restrict__ out){
    __shared__ __align__(16) unsigned char sm2[21504];
    float* sepi = (float*)sm2;
    int tid = threadIdx.x, w = tid >> 5, lane = tid & 31;
    int g = lane >> 2, tg = lane & 3;
    int row0 = blockIdx.x * 64;
    uint32_t sbase = (uint32_t)__cvta_generic_to_shared(sm2);

    int rlo = w*16 + g, rhi = rlo + 8;
    float f1lo = g_f1b[row0 + rlo];
    float f1hi = g_f1b[row0 + rhi];
    float mx = fdec(g_f2max2u[0]);
    float tlo = f1lo + mx, thi = f1hi + mx;
    uint32_t f1lo2 = pack2f(f1lo, f1lo), f1hi2 = pack2f(f1hi, f1hi);
    float gplo = tlo >= 0.f ? 1.f : expf(0.99f*tlo);
    float gnlo = tlo >= 0.f ? expf(-0.99f*tlo) : 1.f;
    float gphi = thi >= 0.f ? 1.f : expf(0.99f*thi);
    float gnhi = thi >= 0.f ? expf(-0.99f*thi) : 1.f;
    uint32_t gplo2 = pack2f(gplo, gplo), gnlo2 = pack2f(gnlo, gnlo);
    uint32_t gphi2 = pack2f(gphi, gphi), gnhi2 = pack2f(gnhi, gnhi);

    int pj = (tid & 48) + permj(tid & 15);   // for tid<64 staging

    float C[4][4] = {};

    // prologue stage tile 0
    if (tid < 64){
        const uint4* src = reinterpret_cast<const uint4*>(g_G2b + (size_t)pj*32);
        uint4* dst = reinterpret_cast<uint4*>(A2_B(0) + tid*80);
#pragma unroll
        for (int q = 0; q < 4; q++) dst[q] = src[q];
        if (tid < 32) A2_T(0)[tid] = g_bd2h[tid];
    } else {
        int u = tid - 64;
        const uint4* src = reinterpret_cast<const uint4*>(g_adj8 + (size_t)(row0 + u)*NN);
        uint4* dst = reinterpret_cast<uint4*>(A2_ADJ(0) + u*80);
#pragma unroll
        for (int q = 0; q < 4; q++) dst[q] = src[q];
    }
    __syncthreads();

    for (int t = 0; t < 64; t++){
        int p = t & 1;
        if (t < 63){
            if (tid < 64){
                const uint4* src = reinterpret_cast<const uint4*>(
                    g_G2b + (size_t)((t+1)*64 + pj)*32);
                uint4* dst = reinterpret_cast<uint4*>(A2_B(p^1) + tid*80);
#pragma unroll
                for (int q = 0; q < 4; q++) dst[q] = src[q];
                if (tid < 32) A2_T(p^1)[tid] = g_bd2h[(t+1)*32 + tid];
            } else {
                int u = tid - 64;
                const uint4* src = reinterpret_cast<const uint4*>(
                    g_adj8 + (size_t)(row0 + u)*NN + (t+1)*64);
                uint4* dst = reinterpret_cast<uint4*>(A2_ADJ(p^1) + u*80);
#pragma unroll
                for (int q = 0; q < 4; q++) dst[q] = src[q];
            }
        }
        const uint4* sT = A2_T(p);
        const unsigned char* adjp = A2_ADJ(p);
        uint32_t Bb = sbase + p*5120;
#pragma unroll
        for (int ks = 0; ks < 4; ks++){
            uint4 T0 = sT[ks*8 + 2*tg];
            uint4 T1 = sT[ks*8 + 2*tg + 1];
            uint32_t vlo = *reinterpret_cast<const uint32_t*>(adjp + rlo*80 + ks*16 + tg*4);
            uint32_t vhi = *reinterpret_cast<const uint32_t*>(adjp + rhi*80 + ks*16 + tg*4);
            uint32_t a0 = wgt_h2(f1lo2, gplo2, gnlo2, T0) & bmask(vlo);
            uint32_t a1 = wgt_h2(f1hi2, gphi2, gnhi2, T0) & bmask(vhi);
            uint32_t a2 = wgt_h2(f1lo2, gplo2, gnlo2, T1) & bmask(vlo >> 16);
            uint32_t a3 = wgt_h2(f1hi2, gphi2, gnhi2, T1) & bmask(vhi >> 16);
            uint32_t lb = Bb + (ks*16 + (lane & 15))*80 + (lane >> 4)*16;
#pragma unroll
            for (int g5 = 0; g5 < 2; g5++){
                uint32_t b0, b1, b2, b3;
                LDSM_X4T(b0, b1, b2, b3, lb + g5*32);
                MMA16816(C[2*g5],     a0, a1, a2, a3, b0, b1);
                MMA16816(C[2*g5 + 1], a0, a1, a2, a3, b2, b3);
            }
        }
        __syncthreads();
    }
    // epilogue
#pragma unroll
    for (int q = 0; q < 4; q++){
        sepi[rlo*32 + q*8 + 2*tg]     = C[q][0];
        sepi[rlo*32 + q*8 + 2*tg + 1] = C[q][1];
        sepi[rhi*32 + q*8 + 2*tg]     = C[q][2];
        sepi[rhi*32 + q*8 + 2*tg + 1] = C[q][3];
    }
    __syncthreads();
    {
        int r = tid >> 1, cg = (tid & 1)*8;
        float rz = 1.f / sepi[r*32 + 16];
        float o[4];
#pragma unroll
        for (int e = 0; e < 4; e++) o[e] = sepi[r*32 + cg + e] * rz;
        *reinterpret_cast<float4*>(out + (size_t)(row0 + r)*NC + cg)
            = make_float4(o[0], o[1], o[2], o[3]);
        float o2[4];
#pragma unroll
        for (int e = 0; e < 4; e++) o2[e] = sepi[r*32 + cg + 4 + e] * rz;
        *reinterpret_cast<float4*>(out + (size_t)(row0 + r)*NC + cg + 4)
            = make_float4(o2[0], o2[1], o2[2], o2[3]);
    }
}

// ---------------- launch ------------------------------------------------------
extern "C" void kernel_launch(void* const* d_in, const int* in_sizes, int n_in,
                              void* d_out, int out_size){
    const float* x    = (const float*)d_in[0];
    const int*   adj  = (const int*)  d_in[1];
    const float* W1   = (const float*)d_in[2];
    const float* a1_1 = (const float*)d_in[3];
    const float* a2_1 = (const float*)d_in[4];
    const float* W2   = (const float*)d_in[5];
    const float* a1_2 = (const float*)d_in[6];
    const float* a2_2 = (const float*)d_in[7];
    float* out = (float*)d_out;

    static int smem_set = 0;
    if (!smem_set){
        cudaFuncSetAttribute(attn1_mma_kernel,
                             cudaFuncAttributeMaxDynamicSharedMemorySize, A1_TOT);
        smem_set = 1;
    }

    adj8_kernel<<<4096, 256>>>(adj);
    gemm1_kernel<<<dim3(64, NH), 256>>>(x, W1, a1_1, a2_1);
    vbf_kernel<<<dim3(64, NH), 256>>>();
    attn1_mma_kernel<<<dim3(64, NH), 128, A1_TOT>>>();
    gemm2_kernel<<<256, 256>>>(W2, a1_2, a2_2);
    bdf2g2_kernel<<<16, 256>>>();
    attn2_mma_kernel<<<64, 128>>>(out);
}

// round 15
// speedup vs baseline: 1.1211x; 1.1211x over previous
#include <cuda_runtime.h>
#include <cuda_fp16.h>
#include <mma.h>
#include <math.h>
#include <stdint.h>

using namespace nvcuda;

#define NN 4096
#define ND 256
#define HID 64
#define NH 4
#define NC 16

// ---------------- scratch (static device globals) ---------------------------
__device__ float  g_H1[NN*ND];
__device__ float  g_F1[NH*NN];
__device__ float  g_F2[NH*NN];
__device__ unsigned g_f2max1u[NH];
__device__ uint8_t g_adj8[(size_t)NN*NN];
__device__ uint4  g_bd1h[NH*2048];           // per j-pair packed half2 {f2,B,D,0}
__device__ __half g_Vb[(size_t)NH*NN*80];    // [head][j][80] (col64 = ones)
__device__ float  g_H2[NN*ND];
__device__ float  g_G2[NN*NC];
__device__ __half g_G2b[NN*32];              // [j][32] (col16 = ones)
__device__ uint4  g_bd2h[2048];
__device__ float  g_f1b[NN];
__device__ float  g_f2b[NN];
__device__ unsigned g_f2max2u[1];

// ---------------- helpers -----------------------------------------------------
__device__ __forceinline__ unsigned fenc(float f){
    unsigned u = __float_as_uint(f);
    return (u & 0x80000000u) ? ~u : (u | 0x80000000u);
}
__device__ __forceinline__ float fdec(unsigned u){
    return (u & 0x80000000u) ? __uint_as_float(u ^ 0x80000000u) : __uint_as_float(~u);
}
__device__ __forceinline__ uint32_t pack2f(float a, float b){
    __half2 h = __floats2half2_rn(a, b);
    return *reinterpret_cast<uint32_t*>(&h);
}
__device__ __forceinline__ __half2 u2h(uint32_t u){ return *reinterpret_cast<__half2*>(&u); }
__device__ __forceinline__ uint32_t h2u(__half2 h){ return *reinterpret_cast<uint32_t*>(&h); }

// ---------------- K0: adjacency -> bytes (+ init atomic cells) ----------------
__global__ void adj8_kernel(const int* __restrict__ adj){
    if (blockIdx.x == 0 && threadIdx.x <= NH){
        if (threadIdx.x < NH) g_f2max1u[threadIdx.x] = 0u;
        else g_f2max2u[0] = 0u;
    }
    size_t idx = (size_t)blockIdx.x*256 + threadIdx.x;   // grid 4096
    const int4* s = reinterpret_cast<const int4*>(adj) + idx*4;
    uint32_t w[4];
#pragma unroll
    for (int q = 0; q < 4; q++){
        int4 v = s[q];
        w[q] = (v.x != 0 ? 1u : 0u) | (v.y != 0 ? 1u : 0u) << 8
             | (v.z != 0 ? 1u : 0u) << 16 | (v.w != 0 ? 1u : 0u) << 24;
    }
    reinterpret_cast<uint4*>(g_adj8)[idx] = make_uint4(w[0], w[1], w[2], w[3]);
}

// ---------------- K1: H1 = x @ W1^T, fused f1/f2 + per-head max ---------------
__global__ void gemm1_kernel(const float* __restrict__ X, const float* __restrict__ W,
                             const float* __restrict__ A1, const float* __restrict__ A2){
    __shared__ float sx[64][17];
    __shared__ float sw[64][17];
    __shared__ float sa1[64], sa2[64], smaxs[16];
    int tid = threadIdx.x;
    int tx = tid & 15, ty = tid >> 4;
    int mb = blockIdx.x * 64, h = blockIdx.y, nb = h * 64;
    if (tid < 64) sa1[tid] = A1[nb + tid];
    else if (tid < 128) sa2[tid - 64] = A2[nb + tid - 64];
    float acc[4][4] = {};
    for (int kb = 0; kb < ND; kb += 16){
        __syncthreads();
        for (int u = tid; u < 64*16; u += 256){
            int m = u >> 4, k = u & 15;
            sx[m][k] = X[(mb + m)*ND + kb + k];
        }
        for (int u = tid; u < 64*16; u += 256){
            int n = u >> 4, k = u & 15;
            sw[n][k] = W[(nb + n)*ND + kb + k];
        }
        __syncthreads();
#pragma unroll
        for (int k = 0; k < 16; k++){
            float a[4], b[4];
#pragma unroll
            for (int r = 0; r < 4; r++){ a[r] = sx[ty*4 + r][k]; b[r] = sw[tx*4 + r][k]; }
#pragma unroll
            for (int i = 0; i < 4; i++)
#pragma unroll
                for (int j = 0; j < 4; j++) acc[i][j] += a[i]*b[j];
        }
    }
#pragma unroll
    for (int i = 0; i < 4; i++)
#pragma unroll
        for (int j = 0; j < 4; j++)
            g_H1[(mb + ty*4 + i)*ND + nb + tx*4 + j] = acc[i][j];
    float a1v[4], a2v[4];
#pragma unroll
    for (int j = 0; j < 4; j++){ a1v[j] = sa1[tx*4 + j]; a2v[j] = sa2[tx*4 + j]; }
    float fmax_local = -INFINITY;
#pragma unroll
    for (int i = 0; i < 4; i++){
        float p1 = acc[i][0]*a1v[0] + acc[i][1]*a1v[1] + acc[i][2]*a1v[2] + acc[i][3]*a1v[3];
        float p2 = acc[i][0]*a2v[0] + acc[i][1]*a2v[1] + acc[i][2]*a2v[2] + acc[i][3]*a2v[3];
#pragma unroll
        for (int off = 8; off > 0; off >>= 1){
            p1 += __shfl_down_sync(0xffffffffu, p1, off, 16);
            p2 += __shfl_down_sync(0xffffffffu, p2, off, 16);
        }
        if (tx == 0){
            int row = mb + ty*4 + i;
            g_F1[h*NN + row] = p1;
            g_F2[h*NN + row] = p2;
            fmax_local = fmaxf(fmax_local, p2);
        }
    }
    if (tx == 0) smaxs[ty] = fmax_local;
    __syncthreads();
    if (tid == 0){
        float m = smaxs[0];
#pragma unroll
        for (int k = 1; k < 16; k++) m = fmaxf(m, smaxs[k]);
        atomicMax(&g_f2max1u[h], fenc(m));
    }
}

// ---------------- K2: V fp16 + ones column, packed bdf table ------------------
__global__ void vbf_kernel(){
    __shared__ float sf[64], sB[64], sD[64];
    int tid = threadIdx.x;            // grid (64, NH), 256 threads
    int jb = blockIdx.x, h = blockIdx.y;
    if (tid < 64){
        int j = jb*64 + tid;
        float f2 = g_F2[h*NN + j];
        float d  = f2 - fdec(g_f2max1u[h]);
        sf[tid] = f2; sB[tid] = expf(d); sD[tid] = expf(0.01f*d);
    }
    __syncthreads();
    if (tid < 32){
        uint4 T;
        T.x = pack2f(sf[2*tid], sf[2*tid + 1]);
        T.y = pack2f(sB[2*tid], sB[2*tid + 1]);
        T.z = pack2f(sD[2*tid], sD[2*tid + 1]);
        T.w = 0u;
        g_bd1h[h*2048 + jb*32 + tid] = T;
    }
    int j = jb*64 + (tid >> 2);
    int fg = tid & 3;
    const float4* src = reinterpret_cast<const float4*>(g_H1 + (size_t)j*ND + h*HID + fg*16);
    __half* dhi = g_Vb + ((size_t)h*NN + j)*80 + fg*16;
    uint32_t ph[8];
#pragma unroll
    for (int q = 0; q < 4; q++){
        float4 v = src[q];
        ph[q*2]   = pack2f(v.x, v.y);
        ph[q*2+1] = pack2f(v.z, v.w);
    }
    uint4* oh = reinterpret_cast<uint4*>(dhi);
    oh[0] = make_uint4(ph[0],ph[1],ph[2],ph[3]);
    oh[1] = make_uint4(ph[4],ph[5],ph[6],ph[7]);
    if (fg == 3){
        uint4* zh = reinterpret_cast<uint4*>(dhi + 16);
        zh[0] = make_uint4(0x00003C00u, 0u, 0u, 0u);
        zh[1] = make_uint4(0u, 0u, 0u, 0u);
    }
}

// ---------------- fp16x2 phase-A weight producer ------------------------------
// 32 fp16 weights (one row, jg half) -> dstA row stride 72 halves
__device__ __forceinline__ void produce_row_h2(
    const uint8_t* adjrow_t, const uint4* sT,
    uint32_t f1h2, uint32_t gp2, uint32_t gn2,
    int jg, __half* dstA, int row)
{
    uint4 a0 = *reinterpret_cast<const uint4*>(adjrow_t + jg*32);
    uint4 a1 = *reinterpret_cast<const uint4*>(adjrow_t + jg*32 + 16);
    uint32_t aw[8] = {a0.x, a0.y, a0.z, a0.w, a1.x, a1.y, a1.z, a1.w};
    const __half2 z2 = __float2half2_rn(0.f);
    uint32_t oh[16];
#pragma unroll
    for (int p = 0; p < 16; p++){
        uint4 T = sT[jg*16 + p];
        __half2 s2 = __hadd2(u2h(f1h2), u2h(T.x));
        uint32_t m = __hgt2_mask(s2, z2);
        uint32_t wp = h2u(__hmul2(u2h(gp2), u2h(T.y)));
        uint32_t wn = h2u(__hmul2(u2h(gn2), u2h(T.z)));
        uint32_t sel = (wp & m) | (wn & ~m);
        uint32_t word = aw[p >> 1], sh = (p & 1)*16;
        uint32_t b0 = (word >> sh) & 0xFFu;
        uint32_t b1 = (word >> (sh + 8)) & 0xFFu;
        oh[p] = sel & (b0*0xFFFFu + b1*0xFFFF0000u);
    }
    uint4* dh = reinterpret_cast<uint4*>(dstA + row*72 + jg*32);
    dh[0] = make_uint4(oh[0], oh[1], oh[2], oh[3]);
    dh[1] = make_uint4(oh[4], oh[5], oh[6], oh[7]);
    dh[2] = make_uint4(oh[8], oh[9], oh[10], oh[11]);
    dh[3] = make_uint4(oh[12], oh[13], oh[14], oh[15]);
}

// ---------------- K3: attn1 pipelined wmma, padded tiles (R12 champion) -------
// dyn smem: AH[2][64][72] 18432 | BH[2][64][88] 22528 | T[2][32]u4 1024 = 41984
#define A1_AH(b)  ((__half*)(dsm + (b)*9216))
#define A1_BH(b)  ((__half*)(dsm + 18432 + (b)*11264))
#define A1_T(b)   ((uint4*)(dsm + 40960 + (b)*512))
#define A1_TOT    41984

__global__ void __launch_bounds__(256, 3) attn1_wmma_kernel(){
    extern __shared__ __align__(16) unsigned char dsm[];
    float* sepi = (float*)dsm;

    int tid = threadIdx.x;
    int wid = tid >> 5;
    int row0 = blockIdx.x * 64;
    int h = blockIdx.y;
    const __half* Vh = g_Vb + (size_t)h*NN*80;
    const uint4* bdg = g_bd1h + h*2048;

    int tp = tid - 128;
    int prow = tp >> 1, pjg = tp & 1;
    uint32_t f1h2 = 0, gp2 = 0, gn2 = 0;
    const uint8_t* adjrow = nullptr;
    if (tid >= 128){
        float f1 = g_F1[h*NN + row0 + prow];
        float tt = f1 + fdec(g_f2max1u[h]);
        float gp = tt >= 0.f ? 1.f : expf(0.99f*tt);
        float gn = tt >= 0.f ? expf(-0.99f*tt) : 1.f;
        f1h2 = pack2f(f1, f1); gp2 = pack2f(gp, gp); gn2 = pack2f(gn, gn);
        adjrow = g_adj8 + (size_t)(row0 + prow)*NN;
    }

    wmma::fragment<wmma::accumulator,16,16,16,float> G[5];
#pragma unroll
    for (int nt = 0; nt < 5; nt++) wmma::fill_fragment(G[nt], 0.f);

    if (tid < 32) A1_T(0)[tid] = bdg[tid];
    __syncthreads();
    if (tid >= 128){
        produce_row_h2(adjrow, A1_T(0), f1h2, gp2, gn2, pjg, A1_AH(0), prow);
        if (tp < 32) A1_T(1)[tp] = bdg[32 + tp];
    } else {
        int j = tid >> 1, ch = (tid & 1)*40;
        const uint4* sh4 = reinterpret_cast<const uint4*>(Vh + (size_t)j*80 + ch);
        uint4* dh4 = reinterpret_cast<uint4*>(A1_BH(0) + j*88 + ch);
#pragma unroll
        for (int q = 0; q < 5; q++) dh4[q] = sh4[q];
    }
    __syncthreads();

    for (int t = 0; t < 64; t++){
        int p = t & 1;
        if (tid >= 128){
            if (t < 63)
                produce_row_h2(adjrow + (t+1)*64, A1_T(p^1), f1h2, gp2, gn2,
                               pjg, A1_AH(p^1), prow);
            if (t < 62 && tp < 32) A1_T(p)[tp] = bdg[(t+2)*32 + tp];
        } else {
            if (t < 63){
                int j = tid >> 1, ch = (tid & 1)*40;
                size_t jb = (size_t)((t+1)*64 + j)*80 + ch;
                const uint4* sh4 = reinterpret_cast<const uint4*>(Vh + jb);
                uint4* dh4 = reinterpret_cast<uint4*>(A1_BH(p^1) + j*88 + ch);
#pragma unroll
                for (int q = 0; q < 5; q++) dh4[q] = sh4[q];
            }
            const __half* Ab = A1_AH(p) + wid*16*72;
            const __half* Bh = A1_BH(p);
#pragma unroll
            for (int ks = 0; ks < 4; ks++){
                wmma::fragment<wmma::matrix_a,16,16,16,__half,wmma::row_major> ah;
                wmma::load_matrix_sync(ah, Ab + ks*16, 72);
#pragma unroll
                for (int nt = 0; nt < 5; nt++){
                    wmma::fragment<wmma::matrix_b,16,16,16,__half,wmma::row_major> bh;
                    wmma::load_matrix_sync(bh, Bh + ks*16*88 + nt*16, 88);
                    wmma::mma_sync(G[nt], ah, bh, G[nt]);
                }
            }
        }
        __syncthreads();
    }
    if (wid < 4){
#pragma unroll
        for (int nt = 0; nt < 5; nt++)
            wmma::store_matrix_sync(sepi + wid*16*80 + nt*16, G[nt], 80, wmma::mem_row_major);
    }
    __syncthreads();
    {
        int r = tid >> 2, cg = (tid & 3)*16;
        float rz = 1.f / sepi[r*80 + 64];
        float* dst = g_H2 + (size_t)(row0 + r)*ND + h*HID + cg;
#pragma unroll
        for (int c = 0; c < 16; c += 4){
            float o[4];
#pragma unroll
            for (int e = 0; e < 4; e++){
                float v = sepi[r*80 + cg + c + e] * rz;
                o[e] = v > 0.f ? v : expm1f(v);
            }
            *reinterpret_cast<float4*>(dst + c) = make_float4(o[0], o[1], o[2], o[3]);
        }
    }
}

// ---------------- K4: G2 = H2 @ W2^T + f-vectors + fused max ------------------
__global__ void gemm2_kernel(const float* __restrict__ W2,
                             const float* __restrict__ a1, const float* __restrict__ a2){
    __shared__ float sW[16][257];
    __shared__ float sa1[16], sa2[16];
    __shared__ float s_u2[16];
    int tid = threadIdx.x;
    for (int u = tid; u < 16*256; u += 256) sW[u >> 8][u & 255] = W2[u];
    if (tid < 16){ sa1[tid] = a1[tid]; sa2[tid] = a2[tid]; }
    __syncthreads();
    int idx = blockIdx.x*256 + tid;
    int i = idx >> 4, c = idx & 15;
    const float4* hr = reinterpret_cast<const float4*>(g_H2 + i*ND);
    float acc = 0.f;
#pragma unroll 4
    for (int k4 = 0; k4 < 64; k4++){
        float4 v = hr[k4];
        acc += v.x*sW[c][k4*4] + v.y*sW[c][k4*4+1] + v.z*sW[c][k4*4+2] + v.w*sW[c][k4*4+3];
    }
    g_G2[idx] = acc;
    float u1 = acc*sa1[c], u2 = acc*sa2[c];
#pragma unroll
    for (int off = 8; off > 0; off >>= 1){
        u1 += __shfl_down_sync(0xffffffffu, u1, off, 16);
        u2 += __shfl_down_sync(0xffffffffu, u2, off, 16);
    }
    if (c == 0){ g_f1b[i] = u1; g_f2b[i] = u2; s_u2[tid >> 4] = u2; }
    __syncthreads();
    if (tid == 0){
        float m = s_u2[0];
#pragma unroll
        for (int k = 1; k < 16; k++) m = fmaxf(m, s_u2[k]);
        atomicMax(g_f2max2u, fenc(m));
    }
}

// ---------------- K5: packed bdf2 table + G2 fp16 split -----------------------
__global__ void bdf2g2_kernel(){
    int row = blockIdx.x*256 + threadIdx.x;   // grid 16
    float f2 = g_f2b[row];
    float d  = f2 - fdec(g_f2max2u[0]);
    float B = expf(d), D = expf(0.01f*d);
    float f2n = __shfl_down_sync(0xffffffffu, f2, 1);
    float Bn  = __shfl_down_sync(0xffffffffu, B, 1);
    float Dn  = __shfl_down_sync(0xffffffffu, D, 1);
    if (!(row & 1)){
        uint4 T;
        T.x = pack2f(f2, f2n); T.y = pack2f(B, Bn); T.z = pack2f(D, Dn); T.w = 0u;
        g_bd2h[row >> 1] = T;
    }
    const float4* src = reinterpret_cast<const float4*>(g_G2 + row*NC);
    uint32_t ph[16];
#pragma unroll
    for (int q = 0; q < 4; q++){
        float4 v = src[q];
        ph[q*2]   = pack2f(v.x, v.y);
        ph[q*2+1] = pack2f(v.z, v.w);
    }
    ph[8] = 0x00003C00u;
#pragma unroll
    for (int k = 9; k < 16; k++) ph[k] = 0u;
    uint4* dh = reinterpret_cast<uint4*>(g_G2b + (size_t)row*32);
#pragma unroll
    for (int k = 0; k < 4; k++)
        dh[k] = make_uint4(ph[4*k], ph[4*k+1], ph[4*k+2], ph[4*k+3]);
}

// ---------------- K6: attn2 pipelined wmma, 32-row blocks ---------------------
// grid 128, 128 threads: warps 0-1 consumers (32 rows), warps 2-3 producers.
// static smem: AH[2][32][72] 9216 | BH[2][64][40] 10240 | T[2][32]u4 1024 = 20480
#define A2_AH(b)  ((__half*)(sm2 + (b)*4608))
#define A2_BH(b)  ((__half*)(sm2 + 9216 + (b)*5120))
#define A2_T(b)   ((uint4*)(sm2 + 19456 + (b)*512))

__global__ void __launch_bounds__(128) attn2_wmma_kernel(float* __restrict__ out){
    __shared__ __align__(16) unsigned char sm2[20480];
    float* sepi = (float*)sm2;

    int tid = threadIdx.x;
    int wid = tid >> 5;
    int row0 = blockIdx.x * 32;

    int tp = tid - 64;
    int prow = tp >> 1, pjg = tp & 1;
    uint32_t f1h2 = 0, gp2 = 0, gn2 = 0;
    const uint8_t* adjrow = nullptr;
    if (tid >= 64){
        float f1 = g_f1b[row0 + prow];
        float tt = f1 + fdec(g_f2max2u[0]);
        float gp = tt >= 0.f ? 1.f : expf(0.99f*tt);
        float gn = tt >= 0.f ? expf(-0.99f*tt) : 1.f;
        f1h2 = pack2f(f1, f1); gp2 = pack2f(gp, gp); gn2 = pack2f(gn, gn);
        adjrow = g_adj8 + (size_t)(row0 + prow)*NN;
    }

    wmma::fragment<wmma::accumulator,16,16,16,float> G[2];
    wmma::fill_fragment(G[0], 0.f);
    wmma::fill_fragment(G[1], 0.f);

    if (tid < 32) A2_T(0)[tid] = g_bd2h[tid];
    __syncthreads();
    if (tid >= 64){
        produce_row_h2(adjrow, A2_T(0), f1h2, gp2, gn2, pjg, A2_AH(0), prow);
        if (tp < 32) A2_T(1)[tp] = g_bd2h[32 + tp];
    } else {
        const uint4* src = reinterpret_cast<const uint4*>(g_G2b + (size_t)tid*32);
        uint4* dst = reinterpret_cast<uint4*>(A2_BH(0) + tid*40);
#pragma unroll
        for (int q = 0; q < 4; q++) dst[q] = src[q];
    }
    __syncthreads();

    for (int t = 0; t < 64; t++){
        int p = t & 1;
        if (tid >= 64){
            if (t < 63)
                produce_row_h2(adjrow + (t+1)*64, A2_T(p^1), f1h2, gp2, gn2,
                               pjg, A2_AH(p^1), prow);
            if (t < 62 && tp < 32) A2_T(p)[tp] = g_bd2h[(t+2)*32 + tp];
        } else {
            if (t < 63){
                const uint4* src = reinterpret_cast<const uint4*>(
                    g_G2b + (size_t)((t+1)*64 + tid)*32);
                uint4* dst = reinterpret_cast<uint4*>(A2_BH(p^1) + tid*40);
#pragma unroll
                for (int q = 0; q < 4; q++) dst[q] = src[q];
            }
            const __half* Ab = A2_AH(p) + wid*16*72;
            const __half* Bh = A2_BH(p);
#pragma unroll
            for (int ks = 0; ks < 4; ks++){
                wmma::fragment<wmma::matrix_a,16,16,16,__half,wmma::row_major> ah;
                wmma::load_matrix_sync(ah, Ab + ks*16, 72);
#pragma unroll
                for (int nt = 0; nt < 2; nt++){
                    wmma::fragment<wmma::matrix_b,16,16,16,__half,wmma::row_major> bh;
                    wmma::load_matrix_sync(bh, Bh + ks*16*40 + nt*16, 40);
                    wmma::mma_sync(G[nt], ah, bh, G[nt]);
                }
            }
        }
        __syncthreads();
    }
    if (wid < 2){
        wmma::store_matrix_sync(sepi + wid*16*32,      G[0], 32, wmma::mem_row_major);
        wmma::store_matrix_sync(sepi + wid*16*32 + 16, G[1], 32, wmma::mem_row_major);
    }
    __syncthreads();
    {
        int r = tid >> 2, cg = (tid & 3)*4;
        float rz = 1.f / sepi[r*32 + 16];
        float o[4];
#pragma unroll
        for (int e = 0; e < 4; e++) o[e] = sepi[r*32 + cg + e] * rz;
        *reinterpret_cast<float4*>(out + (size_t)(row0 + r)*NC + cg)
            = make_float4(o[0], o[1], o[2], o[3]);
    }
}

// ---------------- launch ------------------------------------------------------
extern "C" void kernel_launch(void* const* d_in, const int* in_sizes, int n_in,
                              void* d_out, int out_size){
    const float* x    = (const float*)d_in[0];
    const int*   adj  = (const int*)  d_in[1];
    const float* W1   = (const float*)d_in[2];
    const float* a1_1 = (const float*)d_in[3];
    const float* a2_1 = (const float*)d_in[4];
    const float* W2   = (const float*)d_in[5];
    const float* a1_2 = (const float*)d_in[6];
    const float* a2_2 = (const float*)d_in[7];
    float* out = (float*)d_out;

    static int smem_set = 0;
    if (!smem_set){
        cudaFuncSetAttribute(attn1_wmma_kernel,
                             cudaFuncAttributeMaxDynamicSharedMemorySize, A1_TOT);
        smem_set = 1;
    }

    adj8_kernel<<<4096, 256>>>(adj);
    gemm1_kernel<<<dim3(64, NH), 256>>>(x, W1, a1_1, a2_1);
    vbf_kernel<<<dim3(64, NH), 256>>>();
    attn1_wmma_kernel<<<dim3(64, NH), 256, A1_TOT>>>();
    gemm2_kernel<<<256, 256>>>(W2, a1_2, a2_2);
    bdf2g2_kernel<<<16, 256>>>();
    attn2_wmma_kernel<<<128, 128>>>(out);
}

// round 16
// speedup vs baseline: 1.3027x; 1.1620x over previous
#include <cuda_runtime.h>
#include <cuda_fp16.h>
#include <mma.h>
#include <math.h>
#include <stdint.h>

using namespace nvcuda;

#define NN 4096
#define ND 256
#define HID 64
#define NH 4
#define NC 16
#define S1 2            // attn1 j-splits
#define S2 4            // attn2 j-splits

// ---------------- scratch (static device globals) ---------------------------
__device__ float  g_H1[NN*ND];
__device__ float  g_F1[NH*NN];
__device__ float  g_F2[NH*NN];
__device__ unsigned g_f2max1u[NH];
__device__ uint8_t g_adj8[(size_t)NN*NN];
__device__ uint4  g_bd1h[NH*2048];           // per j-pair packed half2 {f2,B,D,0}
__device__ __half g_Vb[(size_t)NH*NN*80];    // [head][j][80] (col64 = ones)
__device__ float  g_P1[(size_t)S1*NH*NN*80]; // attn1 partials (10.5 MB)
__device__ float  g_H2[NN*ND];
__device__ float  g_G2[NN*NC];
__device__ __half g_G2b[NN*32];              // [j][32] (col16 = ones)
__device__ uint4  g_bd2h[2048];
__device__ float  g_P2[(size_t)S2*NN*32];    // attn2 partials (2 MB)
__device__ float  g_f1b[NN];
__device__ float  g_f2b[NN];
__device__ unsigned g_f2max2u[1];

// ---------------- helpers -----------------------------------------------------
__device__ __forceinline__ unsigned fenc(float f){
    unsigned u = __float_as_uint(f);
    return (u & 0x80000000u) ? ~u : (u | 0x80000000u);
}
__device__ __forceinline__ float fdec(unsigned u){
    return (u & 0x80000000u) ? __uint_as_float(u ^ 0x80000000u) : __uint_as_float(~u);
}
__device__ __forceinline__ uint32_t pack2f(float a, float b){
    __half2 h = __floats2half2_rn(a, b);
    return *reinterpret_cast<uint32_t*>(&h);
}
__device__ __forceinline__ __half2 u2h(uint32_t u){ return *reinterpret_cast<__half2*>(&u); }
__device__ __forceinline__ uint32_t h2u(__half2 h){ return *reinterpret_cast<uint32_t*>(&h); }

// ---------------- K0: adjacency -> bytes (+ init atomic cells) ----------------
__global__ void adj8_kernel(const int* __restrict__ adj){
    if (blockIdx.x == 0 && threadIdx.x <= NH){
        if (threadIdx.x < NH) g_f2max1u[threadIdx.x] = 0u;
        else g_f2max2u[0] = 0u;
    }
    size_t idx = (size_t)blockIdx.x*256 + threadIdx.x;   // grid 4096
    const int4* s = reinterpret_cast<const int4*>(adj) + idx*4;
    uint32_t w[4];
#pragma unroll
    for (int q = 0; q < 4; q++){
        int4 v = s[q];
        w[q] = (v.x != 0 ? 1u : 0u) | (v.y != 0 ? 1u : 0u) << 8
             | (v.z != 0 ? 1u : 0u) << 16 | (v.w != 0 ? 1u : 0u) << 24;
    }
    reinterpret_cast<uint4*>(g_adj8)[idx] = make_uint4(w[0], w[1], w[2], w[3]);
}

// ---------------- K1: H1 = x @ W1^T, fused f1/f2 + per-head max ---------------
__global__ void gemm1_kernel(const float* __restrict__ X, const float* __restrict__ W,
                             const float* __restrict__ A1, const float* __restrict__ A2){
    __shared__ float sx[64][17];
    __shared__ float sw[64][17];
    __shared__ float sa1[64], sa2[64], smaxs[16];
    int tid = threadIdx.x;
    int tx = tid & 15, ty = tid >> 4;
    int mb = blockIdx.x * 64, h = blockIdx.y, nb = h * 64;
    if (tid < 64) sa1[tid] = A1[nb + tid];
    else if (tid < 128) sa2[tid - 64] = A2[nb + tid - 64];
    float acc[4][4] = {};
    for (int kb = 0; kb < ND; kb += 16){
        __syncthreads();
        for (int u = tid; u < 64*16; u += 256){
            int m = u >> 4, k = u & 15;
            sx[m][k] = X[(mb + m)*ND + kb + k];
        }
        for (int u = tid; u < 64*16; u += 256){
            int n = u >> 4, k = u & 15;
            sw[n][k] = W[(nb + n)*ND + kb + k];
        }
        __syncthreads();
#pragma unroll
        for (int k = 0; k < 16; k++){
            float a[4], b[4];
#pragma unroll
            for (int r = 0; r < 4; r++){ a[r] = sx[ty*4 + r][k]; b[r] = sw[tx*4 + r][k]; }
#pragma unroll
            for (int i = 0; i < 4; i++)
#pragma unroll
                for (int j = 0; j < 4; j++) acc[i][j] += a[i]*b[j];
        }
    }
#pragma unroll
    for (int i = 0; i < 4; i++)
#pragma unroll
        for (int j = 0; j < 4; j++)
            g_H1[(mb + ty*4 + i)*ND + nb + tx*4 + j] = acc[i][j];
    float a1v[4], a2v[4];
#pragma unroll
    for (int j = 0; j < 4; j++){ a1v[j] = sa1[tx*4 + j]; a2v[j] = sa2[tx*4 + j]; }
    float fmax_local = -INFINITY;
#pragma unroll
    for (int i = 0; i < 4; i++){
        float p1 = acc[i][0]*a1v[0] + acc[i][1]*a1v[1] + acc[i][2]*a1v[2] + acc[i][3]*a1v[3];
        float p2 = acc[i][0]*a2v[0] + acc[i][1]*a2v[1] + acc[i][2]*a2v[2] + acc[i][3]*a2v[3];
#pragma unroll
        for (int off = 8; off > 0; off >>= 1){
            p1 += __shfl_down_sync(0xffffffffu, p1, off, 16);
            p2 += __shfl_down_sync(0xffffffffu, p2, off, 16);
        }
        if (tx == 0){
            int row = mb + ty*4 + i;
            g_F1[h*NN + row] = p1;
            g_F2[h*NN + row] = p2;
            fmax_local = fmaxf(fmax_local, p2);
        }
    }
    if (tx == 0) smaxs[ty] = fmax_local;
    __syncthreads();
    if (tid == 0){
        float m = smaxs[0];
#pragma unroll
        for (int k = 1; k < 16; k++) m = fmaxf(m, smaxs[k]);
        atomicMax(&g_f2max1u[h], fenc(m));
    }
}

// ---------------- K2: V fp16 + ones column, packed bdf table ------------------
__global__ void vbf_kernel(){
    __shared__ float sf[64], sB[64], sD[64];
    int tid = threadIdx.x;            // grid (64, NH), 256 threads
    int jb = blockIdx.x, h = blockIdx.y;
    if (tid < 64){
        int j = jb*64 + tid;
        float f2 = g_F2[h*NN + j];
        float d  = f2 - fdec(g_f2max1u[h]);
        sf[tid] = f2; sB[tid] = expf(d); sD[tid] = expf(0.01f*d);
    }
    __syncthreads();
    if (tid < 32){
        uint4 T;
        T.x = pack2f(sf[2*tid], sf[2*tid + 1]);
        T.y = pack2f(sB[2*tid], sB[2*tid + 1]);
        T.z = pack2f(sD[2*tid], sD[2*tid + 1]);
        T.w = 0u;
        g_bd1h[h*2048 + jb*32 + tid] = T;
    }
    int j = jb*64 + (tid >> 2);
    int fg = tid & 3;
    const float4* src = reinterpret_cast<const float4*>(g_H1 + (size_t)j*ND + h*HID + fg*16);
    __half* dhi = g_Vb + ((size_t)h*NN + j)*80 + fg*16;
    uint32_t ph[8];
#pragma unroll
    for (int q = 0; q < 4; q++){
        float4 v = src[q];
        ph[q*2]   = pack2f(v.x, v.y);
        ph[q*2+1] = pack2f(v.z, v.w);
    }
    uint4* oh = reinterpret_cast<uint4*>(dhi);
    oh[0] = make_uint4(ph[0],ph[1],ph[2],ph[3]);
    oh[1] = make_uint4(ph[4],ph[5],ph[6],ph[7]);
    if (fg == 3){
        uint4* zh = reinterpret_cast<uint4*>(dhi + 16);
        zh[0] = make_uint4(0x00003C00u, 0u, 0u, 0u);
        zh[1] = make_uint4(0u, 0u, 0u, 0u);
    }
}

// ---------------- fp16x2 phase-A weight producer ------------------------------
__device__ __forceinline__ void produce_row_h2(
    const uint8_t* adjrow_t, const uint4* sT,
    uint32_t f1h2, uint32_t gp2, uint32_t gn2,
    int jg, __half* dstA, int row)
{
    uint4 a0 = *reinterpret_cast<const uint4*>(adjrow_t + jg*32);
    uint4 a1 = *reinterpret_cast<const uint4*>(adjrow_t + jg*32 + 16);
    uint32_t aw[8] = {a0.x, a0.y, a0.z, a0.w, a1.x, a1.y, a1.z, a1.w};
    const __half2 z2 = __float2half2_rn(0.f);
    uint32_t oh[16];
#pragma unroll
    for (int p = 0; p < 16; p++){
        uint4 T = sT[jg*16 + p];
        __half2 s2 = __hadd2(u2h(f1h2), u2h(T.x));
        uint32_t m = __hgt2_mask(s2, z2);
        uint32_t wp = h2u(__hmul2(u2h(gp2), u2h(T.y)));
        uint32_t wn = h2u(__hmul2(u2h(gn2), u2h(T.z)));
        uint32_t sel = (wp & m) | (wn & ~m);
        uint32_t word = aw[p >> 1], sh = (p & 1)*16;
        uint32_t b0 = (word >> sh) & 0xFFu;
        uint32_t b1 = (word >> (sh + 8)) & 0xFFu;
        oh[p] = sel & (b0*0xFFFFu + b1*0xFFFF0000u);
    }
    uint4* dh = reinterpret_cast<uint4*>(dstA + row*72 + jg*32);
    dh[0] = make_uint4(oh[0], oh[1], oh[2], oh[3]);
    dh[1] = make_uint4(oh[4], oh[5], oh[6], oh[7]);
    dh[2] = make_uint4(oh[8], oh[9], oh[10], oh[11]);
    dh[3] = make_uint4(oh[12], oh[13], oh[14], oh[15]);
}

// ---------------- K3: attn1 pipelined wmma, j-split ---------------------------
// grid (64, NH, S1), 256 threads. 32 tiles of 64 j per block. Writes raw partials.
#define A1_AH(b)  ((__half*)(dsm + (b)*9216))
#define A1_BH(b)  ((__half*)(dsm + 18432 + (b)*11264))
#define A1_T(b)   ((uint4*)(dsm + 40960 + (b)*512))
#define A1_TOT    41984

__global__ void __launch_bounds__(256) attn1_wmma_kernel(){
    extern __shared__ __align__(16) unsigned char dsm[];
    float* sepi = (float*)dsm;

    int tid = threadIdx.x;
    int wid = tid >> 5;
    int row0 = blockIdx.x * 64;
    int h = blockIdx.y;
    int s = blockIdx.z;
    int jbase = s * (NN/S1);                 // 2048
    int tbase = s * (NN/S1/64);              // 32
    const __half* Vh = g_Vb + (size_t)h*NN*80;
    const uint4* bdg = g_bd1h + h*2048;

    int tp = tid - 128;
    int prow = tp >> 1, pjg = tp & 1;
    uint32_t f1h2 = 0, gp2 = 0, gn2 = 0;
    const uint8_t* adjrow = nullptr;
    if (tid >= 128){
        float f1 = g_F1[h*NN + row0 + prow];
        float tt = f1 + fdec(g_f2max1u[h]);
        float gp = tt >= 0.f ? 1.f : expf(0.99f*tt);
        float gn = tt >= 0.f ? expf(-0.99f*tt) : 1.f;
        f1h2 = pack2f(f1, f1); gp2 = pack2f(gp, gp); gn2 = pack2f(gn, gn);
        adjrow = g_adj8 + (size_t)(row0 + prow)*NN + jbase;
    }

    wmma::fragment<wmma::accumulator,16,16,16,float> G[5];
#pragma unroll
    for (int nt = 0; nt < 5; nt++) wmma::fill_fragment(G[nt], 0.f);

    if (tid < 32) A1_T(0)[tid] = bdg[tbase*32 + tid];
    __syncthreads();
    if (tid >= 128){
        produce_row_h2(adjrow, A1_T(0), f1h2, gp2, gn2, pjg, A1_AH(0), prow);
        if (tp < 32) A1_T(1)[tp] = bdg[(tbase + 1)*32 + tp];
    } else {
        int j = tid >> 1, ch = (tid & 1)*40;
        const uint4* sh4 = reinterpret_cast<const uint4*>(Vh + (size_t)(jbase + j)*80 + ch);
        uint4* dh4 = reinterpret_cast<uint4*>(A1_BH(0) + j*88 + ch);
#pragma unroll
        for (int q = 0; q < 5; q++) dh4[q] = sh4[q];
    }
    __syncthreads();

    const int NT = NN/S1/64;   // 32
    for (int t = 0; t < NT; t++){
        int p = t & 1;
        if (tid >= 128){
            if (t < NT-1)
                produce_row_h2(adjrow + (t+1)*64, A1_T(p^1), f1h2, gp2, gn2,
                               pjg, A1_AH(p^1), prow);
            if (t < NT-2 && tp < 32) A1_T(p)[tp] = bdg[(tbase + t + 2)*32 + tp];
        } else {
            if (t < NT-1){
                int j = tid >> 1, ch = (tid & 1)*40;
                size_t jb = (size_t)(jbase + (t+1)*64 + j)*80 + ch;
                const uint4* sh4 = reinterpret_cast<const uint4*>(Vh + jb);
                uint4* dh4 = reinterpret_cast<uint4*>(A1_BH(p^1) + j*88 + ch);
#pragma unroll
                for (int q = 0; q < 5; q++) dh4[q] = sh4[q];
            }
            const __half* Ab = A1_AH(p) + wid*16*72;
            const __half* Bh = A1_BH(p);
#pragma unroll
            for (int ks = 0; ks < 4; ks++){
                wmma::fragment<wmma::matrix_a,16,16,16,__half,wmma::row_major> ah;
                wmma::load_matrix_sync(ah, Ab + ks*16, 72);
#pragma unroll
                for (int nt = 0; nt < 5; nt++){
                    wmma::fragment<wmma::matrix_b,16,16,16,__half,wmma::row_major> bh;
                    wmma::load_matrix_sync(bh, Bh + ks*16*88 + nt*16, 88);
                    wmma::mma_sync(G[nt], ah, bh, G[nt]);
                }
            }
        }
        __syncthreads();
    }
    if (wid < 4){
#pragma unroll
        for (int nt = 0; nt < 5; nt++)
            wmma::store_matrix_sync(sepi + wid*16*80 + nt*16, G[nt], 80, wmma::mem_row_major);
    }
    __syncthreads();
    {   // write raw partials (incl Z col 64): 64 rows x 80 cols
        int r = tid >> 2, cg = (tid & 3)*20;
        float* dst = g_P1 + (((size_t)s*NH + h)*NN + row0 + r)*80 + cg;
        const float* src = sepi + r*80 + cg;
#pragma unroll
        for (int c = 0; c < 20; c += 4)
            *reinterpret_cast<float4*>(dst + c) = *reinterpret_cast<const float4*>(src + c);
    }
}

// ---------------- K3b: combine attn1 partials + normalize + ELU ---------------
__global__ void combine1_kernel(){
    int idx = blockIdx.x*256 + threadIdx.x;   // grid 1024: [h][row][c4<16]
    int h = idx >> 16;
    int rem = idx & 65535;
    int row = rem >> 4, c4 = (rem & 15)*4;
    size_t b0 = (((size_t)0*NH + h)*NN + row)*80;
    size_t b1 = (((size_t)1*NH + h)*NN + row)*80;
    float4 p0 = *reinterpret_cast<const float4*>(g_P1 + b0 + c4);
    float4 p1 = *reinterpret_cast<const float4*>(g_P1 + b1 + c4);
    float rz = 1.f / (g_P1[b0 + 64] + g_P1[b1 + 64]);
    float o[4] = {(p0.x + p1.x)*rz, (p0.y + p1.y)*rz, (p0.z + p1.z)*rz, (p0.w + p1.w)*rz};
#pragma unroll
    for (int e = 0; e < 4; e++) o[e] = o[e] > 0.f ? o[e] : expm1f(o[e]);
    *reinterpret_cast<float4*>(g_H2 + (size_t)row*ND + h*HID + c4)
        = make_float4(o[0], o[1], o[2], o[3]);
}

// ---------------- K4: G2 = H2 @ W2^T + f-vectors + fused max ------------------
__global__ void gemm2_kernel(const float* __restrict__ W2,
                             const float* __restrict__ a1, const float* __restrict__ a2){
    __shared__ float sW[16][257];
    __shared__ float sa1[16], sa2[16];
    __shared__ float s_u2[16];
    int tid = threadIdx.x;
    for (int u = tid; u < 16*256; u += 256) sW[u >> 8][u & 255] = W2[u];
    if (tid < 16){ sa1[tid] = a1[tid]; sa2[tid] = a2[tid]; }
    __syncthreads();
    int idx = blockIdx.x*256 + tid;
    int i = idx >> 4, c = idx & 15;
    const float4* hr = reinterpret_cast<const float4*>(g_H2 + i*ND);
    float acc = 0.f;
#pragma unroll 4
    for (int k4 = 0; k4 < 64; k4++){
        float4 v = hr[k4];
        acc += v.x*sW[c][k4*4] + v.y*sW[c][k4*4+1] + v.z*sW[c][k4*4+2] + v.w*sW[c][k4*4+3];
    }
    g_G2[idx] = acc;
    float u1 = acc*sa1[c], u2 = acc*sa2[c];
#pragma unroll
    for (int off = 8; off > 0; off >>= 1){
        u1 += __shfl_down_sync(0xffffffffu, u1, off, 16);
        u2 += __shfl_down_sync(0xffffffffu, u2, off, 16);
    }
    if (c == 0){ g_f1b[i] = u1; g_f2b[i] = u2; s_u2[tid >> 4] = u2; }
    __syncthreads();
    if (tid == 0){
        float m = s_u2[0];
#pragma unroll
        for (int k = 1; k < 16; k++) m = fmaxf(m, s_u2[k]);
        atomicMax(g_f2max2u, fenc(m));
    }
}

// ---------------- K5: packed bdf2 table + G2 fp16 split -----------------------
__global__ void bdf2g2_kernel(){
    int row = blockIdx.x*256 + threadIdx.x;   // grid 16
    float f2 = g_f2b[row];
    float d  = f2 - fdec(g_f2max2u[0]);
    float B = expf(d), D = expf(0.01f*d);
    float f2n = __shfl_down_sync(0xffffffffu, f2, 1);
    float Bn  = __shfl_down_sync(0xffffffffu, B, 1);
    float Dn  = __shfl_down_sync(0xffffffffu, D, 1);
    if (!(row & 1)){
        uint4 T;
        T.x = pack2f(f2, f2n); T.y = pack2f(B, Bn); T.z = pack2f(D, Dn); T.w = 0u;
        g_bd2h[row >> 1] = T;
    }
    const float4* src = reinterpret_cast<const float4*>(g_G2 + row*NC);
    uint32_t ph[16];
#pragma unroll
    for (int q = 0; q < 4; q++){
        float4 v = src[q];
        ph[q*2]   = pack2f(v.x, v.y);
        ph[q*2+1] = pack2f(v.z, v.w);
    }
    ph[8] = 0x00003C00u;
#pragma unroll
    for (int k = 9; k < 16; k++) ph[k] = 0u;
    uint4* dh = reinterpret_cast<uint4*>(g_G2b + (size_t)row*32);
#pragma unroll
    for (int k = 0; k < 4; k++)
        dh[k] = make_uint4(ph[4*k], ph[4*k+1], ph[4*k+2], ph[4*k+3]);
}

// ---------------- K6: attn2 pipelined wmma, 32-row blocks, j-split ------------
// grid (128, S2), 128 threads: warps 0-1 consumers, 2-3 producers. 16 tiles.
#define A2_AH(b)  ((__half*)(sm2 + (b)*4608))
#define A2_BH(b)  ((__half*)(sm2 + 9216 + (b)*5120))
#define A2_T(b)   ((uint4*)(sm2 + 19456 + (b)*512))

__global__ void __launch_bounds__(128) attn2_wmma_kernel(){
    __shared__ __align__(16) unsigned char sm2[20480];
    float* sepi = (float*)sm2;

    int tid = threadIdx.x;
    int wid = tid >> 5;
    int row0 = blockIdx.x * 32;
    int s = blockIdx.y;
    int jbase = s * (NN/S2);                 // 1024
    int tbase = s * (NN/S2/64);              // 16

    int tp = tid - 64;
    int prow = tp >> 1, pjg = tp & 1;
    uint32_t f1h2 = 0, gp2 = 0, gn2 = 0;
    const uint8_t* adjrow = nullptr;
    if (tid >= 64){
        float f1 = g_f1b[row0 + prow];
        float tt = f1 + fdec(g_f2max2u[0]);
        float gp = tt >= 0.f ? 1.f : expf(0.99f*tt);
        float gn = tt >= 0.f ? expf(-0.99f*tt) : 1.f;
        f1h2 = pack2f(f1, f1); gp2 = pack2f(gp, gp); gn2 = pack2f(gn, gn);
        adjrow = g_adj8 + (size_t)(row0 + prow)*NN + jbase;
    }

    wmma::fragment<wmma::accumulator,16,16,16,float> G[2];
    wmma::fill_fragment(G[0], 0.f);
    wmma::fill_fragment(G[1], 0.f);

    if (tid < 32) A2_T(0)[tid] = g_bd2h[tbase*32 + tid];
    __syncthreads();
    if (tid >= 64){
        produce_row_h2(adjrow, A2_T(0), f1h2, gp2, gn2, pjg, A2_AH(0), prow);
        if (tp < 32) A2_T(1)[tp] = g_bd2h[(tbase + 1)*32 + tp];
    } else {
        const uint4* src = reinterpret_cast<const uint4*>(g_G2b + (size_t)(jbase + tid)*32);
        uint4* dst = reinterpret_cast<uint4*>(A2_BH(0) + tid*40);
#pragma unroll
        for (int q = 0; q < 4; q++) dst[q] = src[q];
    }
    __syncthreads();

    const int NT = NN/S2/64;   // 16
    for (int t = 0; t < NT; t++){
        int p = t & 1;
        if (tid >= 64){
            if (t < NT-1)
                produce_row_h2(adjrow + (t+1)*64, A2_T(p^1), f1h2, gp2, gn2,
                               pjg, A2_AH(p^1), prow);
            if (t < NT-2 && tp < 32) A2_T(p)[tp] = g_bd2h[(tbase + t + 2)*32 + tp];
        } else {
            if (t < NT-1){
                const uint4* src = reinterpret_cast<const uint4*>(
                    g_G2b + (size_t)(jbase + (t+1)*64 + tid)*32);
                uint4* dst = reinterpret_cast<uint4*>(A2_BH(p^1) + tid*40);
#pragma unroll
                for (int q = 0; q < 4; q++) dst[q] = src[q];
            }
            const __half* Ab = A2_AH(p) + wid*16*72;
            const __half* Bh = A2_BH(p);
#pragma unroll
            for (int ks = 0; ks < 4; ks++){
                wmma::fragment<wmma::matrix_a,16,16,16,__half,wmma::row_major> ah;
                wmma::load_matrix_sync(ah, Ab + ks*16, 72);
#pragma unroll
                for (int nt = 0; nt < 2; nt++){
                    wmma::fragment<wmma::matrix_b,16,16,16,__half,wmma::row_major> bh;
                    wmma::load_matrix_sync(bh, Bh + ks*16*40 + nt*16, 40);
                    wmma::mma_sync(G[nt], ah, bh, G[nt]);
                }
            }
        }
        __syncthreads();
    }
    if (wid < 2){
        wmma::store_matrix_sync(sepi + wid*16*32,      G[0], 32, wmma::mem_row_major);
        wmma::store_matrix_sync(sepi + wid*16*32 + 16, G[1], 32, wmma::mem_row_major);
    }
    __syncthreads();
    {   // raw partials: 32 rows x 32 cols
        int r = tid >> 2, cg = (tid & 3)*8;
        float* dst = g_P2 + ((size_t)s*NN + row0 + r)*32 + cg;
        const float* src = sepi + r*32 + cg;
        *reinterpret_cast<float4*>(dst)     = *reinterpret_cast<const float4*>(src);
        *reinterpret_cast<float4*>(dst + 4) = *reinterpret_cast<const float4*>(src + 4);
    }
}

// ---------------- K6b: combine attn2 partials -> logits -----------------------
__global__ void combine2_kernel(float* __restrict__ out){
    int idx = blockIdx.x*256 + threadIdx.x;   // grid 64: [row][c4<4]
    int row = idx >> 2, c4 = (idx & 3)*4;
    float4 acc = make_float4(0.f, 0.f, 0.f, 0.f);
    float z = 0.f;
#pragma unroll
    for (int s = 0; s < S2; s++){
        size_t b = ((size_t)s*NN + row)*32;
        float4 p = *reinterpret_cast<const float4*>(g_P2 + b + c4);
        acc.x += p.x; acc.y += p.y; acc.z += p.z; acc.w += p.w;
        z += g_P2[b + 16];
    }
    float rz = 1.f / z;
    *reinterpret_cast<float4*>(out + (size_t)row*NC + c4)
        = make_float4(acc.x*rz, acc.y*rz, acc.z*rz, acc.w*rz);
}

// ---------------- launch ------------------------------------------------------
extern "C" void kernel_launch(void* const* d_in, const int* in_sizes, int n_in,
                              void* d_out, int out_size){
    const float* x    = (const float*)d_in[0];
    const int*   adj  = (const int*)  d_in[1];
    const float* W1   = (const float*)d_in[2];
    const float* a1_1 = (const float*)d_in[3];
    const float* a2_1 = (const float*)d_in[4];
    const float* W2   = (const float*)d_in[5];
    const float* a1_2 = (const float*)d_in[6];
    const float* a2_2 = (const float*)d_in[7];
    float* out = (float*)d_out;

    static int smem_set = 0;
    if (!smem_set){
        cudaFuncSetAttribute(attn1_wmma_kernel,
                             cudaFuncAttributeMaxDynamicSharedMemorySize, A1_TOT);
        smem_set = 1;
    }

    adj8_kernel<<<4096, 256>>>(adj);
    gemm1_kernel<<<dim3(64, NH), 256>>>(x, W1, a1_1, a2_1);
    vbf_kernel<<<dim3(64, NH), 256>>>();
    attn1_wmma_kernel<<<dim3(64, NH, S1), 256, A1_TOT>>>();
    combine1_kernel<<<1024, 256>>>();
    gemm2_kernel<<<256, 256>>>(W2, a1_2, a2_2);
    bdf2g2_kernel<<<16, 256>>>();
    attn2_wmma_kernel<<<dim3(128, S2), 128>>>();
    combine2_kernel<<<64, 256>>>(out);
}

// round 17
// speedup vs baseline: 1.4174x; 1.0880x over previous
#include <cuda_runtime.h>
#include <cuda_fp16.h>
#include <mma.h>
#include <math.h>
#include <stdint.h>

using namespace nvcuda;

#define NN 4096
#define ND 256
#define HID 64
#define NH 4
#define NC 16
#define S1 2            // attn1 j-splits
#define S2 4            // attn2 j-splits

// ---------------- scratch (static device globals) ---------------------------
__device__ float  g_H1[NN*ND];
__device__ float  g_F1[NH*NN];
__device__ float  g_F2[NH*NN];
__device__ unsigned g_f2max1u[NH];
__device__ uint8_t g_adj8[(size_t)NN*NN];
__device__ uint4  g_bd1h[NH*2048];           // per j-pair packed half2 {f2,B,D,0}
__device__ __half g_Vb[(size_t)NH*NN*80];    // [head][j][80] (col64 = ones, unused by attn1)
__device__ float  g_P1[(size_t)S1*NH*NN*80]; // attn1 partials
__device__ float  g_H2[NN*ND];
__device__ float  g_G2[NN*NC];
__device__ __half g_G2b[NN*32];              // [j][32] (col16 = ones)
__device__ uint4  g_bd2h[2048];
__device__ float  g_P2[(size_t)S2*NN*32];    // attn2 partials
__device__ float  g_f1b[NN];
__device__ float  g_f2b[NN];
__device__ unsigned g_f2max2u[1];

// ---------------- helpers -----------------------------------------------------
__device__ __forceinline__ unsigned fenc(float f){
    unsigned u = __float_as_uint(f);
    return (u & 0x80000000u) ? ~u : (u | 0x80000000u);
}
__device__ __forceinline__ float fdec(unsigned u){
    return (u & 0x80000000u) ? __uint_as_float(u ^ 0x80000000u) : __uint_as_float(~u);
}
__device__ __forceinline__ uint32_t pack2f(float a, float b){
    __half2 h = __floats2half2_rn(a, b);
    return *reinterpret_cast<uint32_t*>(&h);
}
__device__ __forceinline__ __half2 u2h(uint32_t u){ return *reinterpret_cast<__half2*>(&u); }
__device__ __forceinline__ uint32_t h2u(__half2 h){ return *reinterpret_cast<uint32_t*>(&h); }

#define MMA16816(C, a0,a1,a2,a3, b0,b1) \
    asm volatile("mma.sync.aligned.m16n8k16.row.col.f32.f16.f16.f32 " \
        "{%0,%1,%2,%3}, {%4,%5,%6,%7}, {%8,%9}, {%0,%1,%2,%3};" \
        : "+f"((C)[0]), "+f"((C)[1]), "+f"((C)[2]), "+f"((C)[3]) \
        : "r"(a0), "r"(a1), "r"(a2), "r"(a3), "r"(b0), "r"(b1))

#define LDSM_X4T(b0,b1,b2,b3, addr) \
    asm volatile("ldmatrix.sync.aligned.m8n8.x4.trans.shared.b16 {%0,%1,%2,%3}, [%4];" \
        : "=r"(b0), "=r"(b1), "=r"(b2), "=r"(b3) : "r"(addr))

#define LDSM_X4(b0,b1,b2,b3, addr) \
    asm volatile("ldmatrix.sync.aligned.m8n8.x4.shared.b16 {%0,%1,%2,%3}, [%4];" \
        : "=r"(b0), "=r"(b1), "=r"(b2), "=r"(b3) : "r"(addr))

// ---------------- K0: adjacency -> bytes (+ init atomic cells) ----------------
__global__ void adj8_kernel(const int* __restrict__ adj){
    if (blockIdx.x == 0 && threadIdx.x <= NH){
        if (threadIdx.x < NH) g_f2max1u[threadIdx.x] = 0u;
        else g_f2max2u[0] = 0u;
    }
    size_t idx = (size_t)blockIdx.x*256 + threadIdx.x;   // grid 4096
    const int4* s = reinterpret_cast<const int4*>(adj) + idx*4;
    uint32_t w[4];
#pragma unroll
    for (int q = 0; q < 4; q++){
        int4 v = s[q];
        w[q] = (v.x != 0 ? 1u : 0u) | (v.y != 0 ? 1u : 0u) << 8
             | (v.z != 0 ? 1u : 0u) << 16 | (v.w != 0 ? 1u : 0u) << 24;
    }
    reinterpret_cast<uint4*>(g_adj8)[idx] = make_uint4(w[0], w[1], w[2], w[3]);
}

// ---------------- K1: H1 = x @ W1^T, fused f1/f2 + per-head max ---------------
__global__ void gemm1_kernel(const float* __restrict__ X, const float* __restrict__ W,
                             const float* __restrict__ A1, const float* __restrict__ A2){
    __shared__ float sx[64][17];
    __shared__ float sw[64][17];
    __shared__ float sa1[64], sa2[64], smaxs[16];
    int tid = threadIdx.x;
    int tx = tid & 15, ty = tid >> 4;
    int mb = blockIdx.x * 64, h = blockIdx.y, nb = h * 64;
    if (tid < 64) sa1[tid] = A1[nb + tid];
    else if (tid < 128) sa2[tid - 64] = A2[nb + tid - 64];
    float acc[4][4] = {};
    for (int kb = 0; kb < ND; kb += 16){
        __syncthreads();
        for (int u = tid; u < 64*16; u += 256){
            int m = u >> 4, k = u & 15;
            sx[m][k] = X[(mb + m)*ND + kb + k];
        }
        for (int u = tid; u < 64*16; u += 256){
            int n = u >> 4, k = u & 15;
            sw[n][k] = W[(nb + n)*ND + kb + k];
        }
        __syncthreads();
#pragma unroll
        for (int k = 0; k < 16; k++){
            float a[4], b[4];
#pragma unroll
            for (int r = 0; r < 4; r++){ a[r] = sx[ty*4 + r][k]; b[r] = sw[tx*4 + r][k]; }
#pragma unroll
            for (int i = 0; i < 4; i++)
#pragma unroll
                for (int j = 0; j < 4; j++) acc[i][j] += a[i]*b[j];
        }
    }
#pragma unroll
    for (int i = 0; i < 4; i++)
#pragma unroll
        for (int j = 0; j < 4; j++)
            g_H1[(mb + ty*4 + i)*ND + nb + tx*4 + j] = acc[i][j];
    float a1v[4], a2v[4];
#pragma unroll
    for (int j = 0; j < 4; j++){ a1v[j] = sa1[tx*4 + j]; a2v[j] = sa2[tx*4 + j]; }
    float fmax_local = -INFINITY;
#pragma unroll
    for (int i = 0; i < 4; i++){
        float p1 = acc[i][0]*a1v[0] + acc[i][1]*a1v[1] + acc[i][2]*a1v[2] + acc[i][3]*a1v[3];
        float p2 = acc[i][0]*a2v[0] + acc[i][1]*a2v[1] + acc[i][2]*a2v[2] + acc[i][3]*a2v[3];
#pragma unroll
        for (int off = 8; off > 0; off >>= 1){
            p1 += __shfl_down_sync(0xffffffffu, p1, off, 16);
            p2 += __shfl_down_sync(0xffffffffu, p2, off, 16);
        }
        if (tx == 0){
            int row = mb + ty*4 + i;
            g_F1[h*NN + row] = p1;
            g_F2[h*NN + row] = p2;
            fmax_local = fmaxf(fmax_local, p2);
        }
    }
    if (tx == 0) smaxs[ty] = fmax_local;
    __syncthreads();
    if (tid == 0){
        float m = smaxs[0];
#pragma unroll
        for (int k = 1; k < 16; k++) m = fmaxf(m, smaxs[k]);
        atomicMax(&g_f2max1u[h], fenc(m));
    }
}

// ---------------- K2: V fp16 + ones column, packed bdf table ------------------
__global__ void vbf_kernel(){
    __shared__ float sf[64], sB[64], sD[64];
    int tid = threadIdx.x;            // grid (64, NH), 256 threads
    int jb = blockIdx.x, h = blockIdx.y;
    if (tid < 64){
        int j = jb*64 + tid;
        float f2 = g_F2[h*NN + j];
        float d  = f2 - fdec(g_f2max1u[h]);
        sf[tid] = f2; sB[tid] = expf(d); sD[tid] = expf(0.01f*d);
    }
    __syncthreads();
    if (tid < 32){
        uint4 T;
        T.x = pack2f(sf[2*tid], sf[2*tid + 1]);
        T.y = pack2f(sB[2*tid], sB[2*tid + 1]);
        T.z = pack2f(sD[2*tid], sD[2*tid + 1]);
        T.w = 0u;
        g_bd1h[h*2048 + jb*32 + tid] = T;
    }
    int j = jb*64 + (tid >> 2);
    int fg = tid & 3;
    const float4* src = reinterpret_cast<const float4*>(g_H1 + (size_t)j*ND + h*HID + fg*16);
    __half* dhi = g_Vb + ((size_t)h*NN + j)*80 + fg*16;
    uint32_t ph[8];
#pragma unroll
    for (int q = 0; q < 4; q++){
        float4 v = src[q];
        ph[q*2]   = pack2f(v.x, v.y);
        ph[q*2+1] = pack2f(v.z, v.w);
    }
    uint4* oh = reinterpret_cast<uint4*>(dhi);
    oh[0] = make_uint4(ph[0],ph[1],ph[2],ph[3]);
    oh[1] = make_uint4(ph[4],ph[5],ph[6],ph[7]);
    if (fg == 3){
        uint4* zh = reinterpret_cast<uint4*>(dhi + 16);
        zh[0] = make_uint4(0x00003C00u, 0u, 0u, 0u);
        zh[1] = make_uint4(0u, 0u, 0u, 0u);
    }
}

// ---------------- fp16x2 phase-A weight producer ------------------------------
__device__ __forceinline__ void produce_row_h2(
    const uint8_t* adjrow_t, const uint4* sT,
    uint32_t f1h2, uint32_t gp2, uint32_t gn2,
    int jg, __half* dstA, int row)
{
    uint4 a0 = *reinterpret_cast<const uint4*>(adjrow_t + jg*32);
    uint4 a1 = *reinterpret_cast<const uint4*>(adjrow_t + jg*32 + 16);
    uint32_t aw[8] = {a0.x, a0.y, a0.z, a0.w, a1.x, a1.y, a1.z, a1.w};
    const __half2 z2 = __float2half2_rn(0.f);
    uint32_t oh[16];
#pragma unroll
    for (int p = 0; p < 16; p++){
        uint4 T = sT[jg*16 + p];
        __half2 s2 = __hadd2(u2h(f1h2), u2h(T.x));
        uint32_t m = __hgt2_mask(s2, z2);
        uint32_t wp = h2u(__hmul2(u2h(gp2), u2h(T.y)));
        uint32_t wn = h2u(__hmul2(u2h(gn2), u2h(T.z)));
        uint32_t sel = (wp & m) | (wn & ~m);
        uint32_t word = aw[p >> 1], sh = (p & 1)*16;
        uint32_t b0 = (word >> sh) & 0xFFu;
        uint32_t b1 = (word >> (sh + 8)) & 0xFFu;
        oh[p] = sel & (b0*0xFFFFu + b1*0xFFFF0000u);
    }
    uint4* dh = reinterpret_cast<uint4*>(dstA + row*72 + jg*32);
    dh[0] = make_uint4(oh[0], oh[1], oh[2], oh[3]);
    dh[1] = make_uint4(oh[4], oh[5], oh[6], oh[7]);
    dh[2] = make_uint4(oh[8], oh[9], oh[10], oh[11]);
    dh[3] = make_uint4(oh[12], oh[13], oh[14], oh[15]);
}

// ---------------- K3: attn1 — 2 MMA warps + 4 producers + 2 stagers ----------
// grid (64, NH, S1), 256 threads.
// dyn smem: AH[2][64][72] (9216 ea) | BH[2][64][72] (9216 ea) | T[2][32]u4
#define A1_AH(b)  ((__half*)(dsm + (b)*9216))
#define A1_BH(b)  ((__half*)(dsm + 18432 + (b)*9216))
#define A1_T(b)   ((uint4*)(dsm + 36864 + (b)*512))
#define A1_TOT    37888

__global__ void __launch_bounds__(256) attn1_mma_kernel(){
    extern __shared__ __align__(16) unsigned char dsm[];
    float* sepi = (float*)dsm;
    uint32_t sbase = (uint32_t)__cvta_generic_to_shared(dsm);

    int tid = threadIdx.x;
    int wid = tid >> 5, lane = tid & 31;
    int row0 = blockIdx.x * 64;
    int h = blockIdx.y;
    int s = blockIdx.z;
    int jbase = s * (NN/S1);
    int tbase = s * (NN/S1/64);
    const __half* Vh = g_Vb + (size_t)h*NN*80;
    const uint4* bdg = g_bd1h + h*2048;
    const int NT = NN/S1/64;   // 32

    // producer identity (wid 2-5): tp in [0,128)
    int tp = tid - 64;
    int prow = tp >> 1, pjg = tp & 1;
    uint32_t f1h2 = 0, gp2 = 0, gn2 = 0;
    const uint8_t* adjrow = nullptr;
    if (wid >= 2 && wid < 6){
        float f1 = g_F1[h*NN + row0 + prow];
        float tt = f1 + fdec(g_f2max1u[h]);
        float gp = tt >= 0.f ? 1.f : expf(0.99f*tt);
        float gn = tt >= 0.f ? expf(-0.99f*tt) : 1.f;
        f1h2 = pack2f(f1, f1); gp2 = pack2f(gp, gp); gn2 = pack2f(gn, gn);
        adjrow = g_adj8 + (size_t)(row0 + prow)*NN + jbase;
    }
    // stager identity (wid 6-7): ts in [0,64)
    int ts = tid - 192;
    // consumer accumulators
    float C[2][8][4] = {};
    float CZ[2][4] = {};
    uint32_t bz = ((lane >> 2) == 0) ? 0x3C003C00u : 0u;

    // ---- prologue ----
    if (tid < 32) A1_T(0)[tid] = bdg[tbase*32 + tid];
    __syncthreads();
    if (wid >= 2 && wid < 6){
        produce_row_h2(adjrow, A1_T(0), f1h2, gp2, gn2, pjg, A1_AH(0), prow);
        if (tp < 32) A1_T(1)[tp] = bdg[(tbase + 1)*32 + tp];
    } else if (wid >= 6){
        const uint4* src = reinterpret_cast<const uint4*>(Vh + (size_t)(jbase + ts)*80);
        uint4* dst = reinterpret_cast<uint4*>(A1_BH(0) + ts*72);
#pragma unroll
        for (int q = 0; q < 8; q++) dst[q] = src[q];
    }
    __syncthreads();

    for (int t = 0; t < NT; t++){
        int p = t & 1;
        if (wid < 2){
            // ---- consumers: tile t ----
            uint32_t Ab = sbase + p*9216;
            uint32_t Bb = sbase + 18432 + p*9216;
#pragma unroll
            for (int ks = 0; ks < 4; ks++){
                uint32_t bf[4][4];
#pragma unroll
                for (int nt = 0; nt < 4; nt++)
                    LDSM_X4T(bf[nt][0], bf[nt][1], bf[nt][2], bf[nt][3],
                             Bb + (ks*16 + (lane & 15))*144 + (lane >> 4)*16 + nt*32);
#pragma unroll
                for (int sub = 0; sub < 2; sub++){
                    uint32_t a0, a1, a2, a3;
                    LDSM_X4(a0, a1, a2, a3,
                        Ab + ((wid*32 + sub*16 + (lane & 15))*72 + ks*16 + (lane >> 4)*8)*2);
#pragma unroll
                    for (int nt = 0; nt < 4; nt++){
                        MMA16816(C[sub][2*nt],     a0, a1, a2, a3, bf[nt][0], bf[nt][1]);
                        MMA16816(C[sub][2*nt + 1], a0, a1, a2, a3, bf[nt][2], bf[nt][3]);
                    }
                    MMA16816(CZ[sub], a0, a1, a2, a3, bz, bz);
                }
            }
        } else if (wid < 6){
            // ---- producers: A(t+1), T(t+2) ----
            if (t < NT-1)
                produce_row_h2(adjrow + (t+1)*64, A1_T(p^1), f1h2, gp2, gn2,
                               pjg, A1_AH(p^1), prow);
            if (t < NT-2 && tp < 32) A1_T(p)[tp] = bdg[(tbase + t + 2)*32 + tp];
        } else {
            // ---- stagers: B(t+1) ----
            if (t < NT-1){
                const uint4* src = reinterpret_cast<const uint4*>(
                    Vh + (size_t)(jbase + (t+1)*64 + ts)*80);
                uint4* dst = reinterpret_cast<uint4*>(A1_BH(p^1) + ts*72);
#pragma unroll
                for (int q = 0; q < 8; q++) dst[q] = src[q];
            }
        }
        __syncthreads();
    }
    // ---- epilogue: consumers dump C to sepi ----
    if (wid < 2){
        int g = lane >> 2, tg = lane & 3;
#pragma unroll
        for (int sub = 0; sub < 2; sub++){
            int r0 = wid*32 + sub*16 + g;
#pragma unroll
            for (int nf = 0; nf < 8; nf++){
                sepi[r0*80 + nf*8 + 2*tg]       = C[sub][nf][0];
                sepi[r0*80 + nf*8 + 2*tg + 1]   = C[sub][nf][1];
                sepi[(r0+8)*80 + nf*8 + 2*tg]     = C[sub][nf][2];
                sepi[(r0+8)*80 + nf*8 + 2*tg + 1] = C[sub][nf][3];
            }
            if (tg == 0){
                sepi[r0*80 + 64]     = CZ[sub][0];
                sepi[(r0+8)*80 + 64] = CZ[sub][2];
            }
        }
    }
    __syncthreads();
    {   // write raw partials (cols 0..63 + Z at 64)
        int r = tid >> 2, cg = (tid & 3)*20;
        float* dst = g_P1 + (((size_t)s*NH + h)*NN + row0 + r)*80 + cg;
        const float* src = sepi + r*80 + cg;
#pragma unroll
        for (int c = 0; c < 20; c += 4)
            *reinterpret_cast<float4*>(dst + c) = *reinterpret_cast<const float4*>(src + c);
    }
}

// ---------------- K3b: combine attn1 partials + normalize + ELU ---------------
__global__ void combine1_kernel(){
    int idx = blockIdx.x*256 + threadIdx.x;   // grid 1024: [h][row][c4<16]
    int h = idx >> 16;
    int rem = idx & 65535;
    int row = rem >> 4, c4 = (rem & 15)*4;
    size_t b0 = (((size_t)0*NH + h)*NN + row)*80;
    size_t b1 = (((size_t)1*NH + h)*NN + row)*80;
    float4 p0 = *reinterpret_cast<const float4*>(g_P1 + b0 + c4);
    float4 p1 = *reinterpret_cast<const float4*>(g_P1 + b1 + c4);
    float rz = 1.f / (g_P1[b0 + 64] + g_P1[b1 + 64]);
    float o[4] = {(p0.x + p1.x)*rz, (p0.y + p1.y)*rz, (p0.z + p1.z)*rz, (p0.w + p1.w)*rz};
#pragma unroll
    for (int e = 0; e < 4; e++) o[e] = o[e] > 0.f ? o[e] : expm1f(o[e]);
    *reinterpret_cast<float4*>(g_H2 + (size_t)row*ND + h*HID + c4)
        = make_float4(o[0], o[1], o[2], o[3]);
}

// ---------------- K4: G2 = H2 @ W2^T + f-vectors + fused max ------------------
__global__ void gemm2_kernel(const float* __restrict__ W2,
                             const float* __restrict__ a1, const float* __restrict__ a2){
    __shared__ float sW[16][257];
    __shared__ float sa1[16], sa2[16];
    __shared__ float s_u2[16];
    int tid = threadIdx.x;
    for (int u = tid; u < 16*256; u += 256) sW[u >> 8][u & 255] = W2[u];
    if (tid < 16){ sa1[tid] = a1[tid]; sa2[tid] = a2[tid]; }
    __syncthreads();
    int idx = blockIdx.x*256 + tid;
    int i = idx >> 4, c = idx & 15;
    const float4* hr = reinterpret_cast<const float4*>(g_H2 + i*ND);
    float acc = 0.f;
#pragma unroll 4
    for (int k4 = 0; k4 < 64; k4++){
        float4 v = hr[k4];
        acc += v.x*sW[c][k4*4] + v.y*sW[c][k4*4+1] + v.z*sW[c][k4*4+2] + v.w*sW[c][k4*4+3];
    }
    g_G2[idx] = acc;
    float u1 = acc*sa1[c], u2 = acc*sa2[c];
#pragma unroll
    for (int off = 8; off > 0; off >>= 1){
        u1 += __shfl_down_sync(0xffffffffu, u1, off, 16);
        u2 += __shfl_down_sync(0xffffffffu, u2, off, 16);
    }
    if (c == 0){ g_f1b[i] = u1; g_f2b[i] = u2; s_u2[tid >> 4] = u2; }
    __syncthreads();
    if (tid == 0){
        float m = s_u2[0];
#pragma unroll
        for (int k = 1; k < 16; k++) m = fmaxf(m, s_u2[k]);
        atomicMax(g_f2max2u, fenc(m));
    }
}

// ---------------- K5: packed bdf2 table + G2 fp16 split -----------------------
__global__ void bdf2g2_kernel(){
    int row = blockIdx.x*256 + threadIdx.x;   // grid 16
    float f2 = g_f2b[row];
    float d  = f2 - fdec(g_f2max2u[0]);
    float B = expf(d), D = expf(0.01f*d);
    float f2n = __shfl_down_sync(0xffffffffu, f2, 1);
    float Bn  = __shfl_down_sync(0xffffffffu, B, 1);
    float Dn  = __shfl_down_sync(0xffffffffu, D, 1);
    if (!(row & 1)){
        uint4 T;
        T.x = pack2f(f2, f2n); T.y = pack2f(B, Bn); T.z = pack2f(D, Dn); T.w = 0u;
        g_bd2h[row >> 1] = T;
    }
    const float4* src = reinterpret_cast<const float4*>(g_G2 + row*NC);
    uint32_t ph[16];
#pragma unroll
    for (int q = 0; q < 4; q++){
        float4 v = src[q];
        ph[q*2]   = pack2f(v.x, v.y);
        ph[q*2+1] = pack2f(v.z, v.w);
    }
    ph[8] = 0x00003C00u;
#pragma unroll
    for (int k = 9; k < 16; k++) ph[k] = 0u;
    uint4* dh = reinterpret_cast<uint4*>(g_G2b + (size_t)row*32);
#pragma unroll
    for (int k = 0; k < 4; k++)
        dh[k] = make_uint4(ph[4*k], ph[4*k+1], ph[4*k+2], ph[4*k+3]);
}

// ---------------- K6: attn2 pipelined wmma, 32-row blocks, j-split ------------
#define A2_AH(b)  ((__half*)(sm2 + (b)*4608))
#define A2_BH(b)  ((__half*)(sm2 + 9216 + (b)*5120))
#define A2_T(b)   ((uint4*)(sm2 + 19456 + (b)*512))

__global__ void __launch_bounds__(128) attn2_wmma_kernel(){
    __shared__ __align__(16) unsigned char sm2[20480];
    float* sepi = (float*)sm2;

    int tid = threadIdx.x;
    int wid = tid >> 5;
    int row0 = blockIdx.x * 32;
    int s = blockIdx.y;
    int jbase = s * (NN/S2);
    int tbase = s * (NN/S2/64);

    int tp = tid - 64;
    int prow = tp >> 1, pjg = tp & 1;
    uint32_t f1h2 = 0, gp2 = 0, gn2 = 0;
    const uint8_t* adjrow = nullptr;
    if (tid >= 64){
        float f1 = g_f1b[row0 + prow];
        float tt = f1 + fdec(g_f2max2u[0]);
        float gp = tt >= 0.f ? 1.f : expf(0.99f*tt);
        float gn = tt >= 0.f ? expf(-0.99f*tt) : 1.f;
        f1h2 = pack2f(f1, f1); gp2 = pack2f(gp, gp); gn2 = pack2f(gn, gn);
        adjrow = g_adj8 + (size_t)(row0 + prow)*NN + jbase;
    }

    wmma::fragment<wmma::accumulator,16,16,16,float> G[2];
    wmma::fill_fragment(G[0], 0.f);
    wmma::fill_fragment(G[1], 0.f);

    if (tid < 32) A2_T(0)[tid] = g_bd2h[tbase*32 + tid];
    __syncthreads();
    if (tid >= 64){
        produce_row_h2(adjrow, A2_T(0), f1h2, gp2, gn2, pjg, A2_AH(0), prow);
        if (tp < 32) A2_T(1)[tp] = g_bd2h[(tbase + 1)*32 + tp];
    } else {
        const uint4* src = reinterpret_cast<const uint4*>(g_G2b + (size_t)(jbase + tid)*32);
        uint4* dst = reinterpret_cast<uint4*>(A2_BH(0) + tid*40);
#pragma unroll
        for (int q = 0; q < 4; q++) dst[q] = src[q];
    }
    __syncthreads();

    const int NT = NN/S2/64;   // 16
    for (int t = 0; t < NT; t++){
        int p = t & 1;
        if (tid >= 64){
            if (t < NT-1)
                produce_row_h2(adjrow + (t+1)*64, A2_T(p^1), f1h2, gp2, gn2,
                               pjg, A2_AH(p^1), prow);
            if (t < NT-2 && tp < 32) A2_T(p)[tp] = g_bd2h[(tbase + t + 2)*32 + tp];
        } else {
            if (t < NT-1){
                const uint4* src = reinterpret_cast<const uint4*>(
                    g_G2b + (size_t)(jbase + (t+1)*64 + tid)*32);
                uint4* dst = reinterpret_cast<uint4*>(A2_BH(p^1) + tid*40);
#pragma unroll
                for (int q = 0; q < 4; q++) dst[q] = src[q];
            }
            const __half* Ab = A2_AH(p) + wid*16*72;
            const __half* Bh = A2_BH(p);
#pragma unroll
            for (int ks = 0; ks < 4; ks++){
                wmma::fragment<wmma::matrix_a,16,16,16,__half,wmma::row_major> ah;
                wmma::load_matrix_sync(ah, Ab + ks*16, 72);
#pragma unroll
                for (int nt = 0; nt < 2; nt++){
                    wmma::fragment<wmma::matrix_b,16,16,16,__half,wmma::row_major> bh;
                    wmma::load_matrix_sync(bh, Bh + ks*16*40 + nt*16, 40);
                    wmma::mma_sync(G[nt], ah, bh, G[nt]);
                }
            }
        }
        __syncthreads();
    }
    if (wid < 2){
        wmma::store_matrix_sync(sepi + wid*16*32,      G[0], 32, wmma::mem_row_major);
        wmma::store_matrix_sync(sepi + wid*16*32 + 16, G[1], 32, wmma::mem_row_major);
    }
    __syncthreads();
    {   // raw partials: 32 rows x 32 cols
        int r = tid >> 2, cg = (tid & 3)*8;
        float* dst = g_P2 + ((size_t)s*NN + row0 + r)*32 + cg;
        const float* src = sepi + r*32 + cg;
        *reinterpret_cast<float4*>(dst)     = *reinterpret_cast<const float4*>(src);
        *reinterpret_cast<float4*>(dst + 4) = *reinterpret_cast<const float4*>(src + 4);
    }
}

// ---------------- K6b: combine attn2 partials -> logits -----------------------
__global__ void combine2_kernel(float* __restrict__ out){
    int idx = blockIdx.x*256 + threadIdx.x;   // grid 64: [row][c4<4]
    int row = idx >> 2, c4 = (idx & 3)*4;
    float4 acc = make_float4(0.f, 0.f, 0.f, 0.f);
    float z = 0.f;
#pragma unroll
    for (int s = 0; s < S2; s++){
        size_t b = ((size_t)s*NN + row)*32;
        float4 p = *reinterpret_cast<const float4*>(g_P2 + b + c4);
        acc.x += p.x; acc.y += p.y; acc.z += p.z; acc.w += p.w;
        z += g_P2[b + 16];
    }
    float rz = 1.f / z;
    *reinterpret_cast<float4*>(out + (size_t)row*NC + c4)
        = make_float4(acc.x*rz, acc.y*rz, acc.z*rz, acc.w*rz);
}

// ---------------- launch ------------------------------------------------------
extern "C" void kernel_launch(void* const* d_in, const int* in_sizes, int n_in,
                              void* d_out, int out_size){
    const float* x    = (const float*)d_in[0];
    const int*   adj  = (const int*)  d_in[1];
    const float* W1   = (const float*)d_in[2];
    const float* a1_1 = (const float*)d_in[3];
    const float* a2_1 = (const float*)d_in[4];
    const float* W2   = (const float*)d_in[5];
    const float* a1_2 = (const float*)d_in[6];
    const float* a2_2 = (const float*)d_in[7];
    float* out = (float*)d_out;

    static int smem_set = 0;
    if (!smem_set){
        cudaFuncSetAttribute(attn1_mma_kernel,
                             cudaFuncAttributeMaxDynamicSharedMemorySize, A1_TOT);
        smem_set = 1;
    }

    adj8_kernel<<<4096, 256>>>(adj);
    gemm1_kernel<<<dim3(64, NH), 256>>>(x, W1, a1_1, a2_1);
    vbf_kernel<<<dim3(64, NH), 256>>>();
    attn1_mma_kernel<<<dim3(64, NH, S1), 256, A1_TOT>>>();
    combine1_kernel<<<1024, 256>>>();
    gemm2_kernel<<<256, 256>>>(W2, a1_2, a2_2);
    bdf2g2_kernel<<<16, 256>>>();
    attn2_wmma_kernel<<<dim3(128, S2), 128>>>();
    combine2_kernel<<<64, 256>>>(out);
}